// round 9
// baseline (speedup 1.0000x reference)
#include <cuda_runtime.h>
#include <cuda_bf16.h>
#include <math.h>
#include <stdint.h>

// ---------------------------------------------------------------------------
// BEiT encoder: B=64, S=197, DM=768, H=12, D=64, DF=3072, L=3
// GEMMs: mma.sync bf16 hi/lo split, 2-stage cp.async (BK=64), SW128,
// 128x64 CTA tile, 2 CTAs/SM, ONE barrier/chunk, fragment double-buffering.
// ---------------------------------------------------------------------------

#define MROWS 12608
#define DM    768
#define DF    3072
#define NQKV  2304
#define SEQ   197
#define NB    64
#define NH    12
#define HD    64
#define NDREL 732

#define TM 128
#define TN 64
#define BK 64

typedef __nv_bfloat16 bf16;

// fp32 scratch
__device__ float g_h   [MROWS * DM];
__device__ float g_qkv [MROWS * NQKV];
__device__ float g_bqkv[NQKV];
// bf16 hi/lo activation planes
__device__ bf16 g_hn_hi [MROWS * DM];
__device__ bf16 g_hn_lo [MROWS * DM];
__device__ bf16 g_ctx_hi[MROWS * DM];
__device__ bf16 g_ctx_lo[MROWS * DM];
__device__ bf16 g_f_hi  [MROWS * DF];
__device__ bf16 g_f_lo  [MROWS * DF];
// transposed weight planes [N][K]
__device__ bf16 g_wqkv_hi[3 * NQKV * DM];
__device__ bf16 g_wqkv_lo[3 * NQKV * DM];
__device__ bf16 g_wo_hi  [3 * DM * DM];
__device__ bf16 g_wo_lo  [3 * DM * DM];
__device__ bf16 g_wi_hi  [3 * DF * DM];
__device__ bf16 g_wi_lo  [3 * DF * DM];
__device__ bf16 g_wmo_hi [3 * DM * DF];
__device__ bf16 g_wmo_lo [3 * DM * DF];

// ---------------------------------------------------------------------------
// helpers
// ---------------------------------------------------------------------------
__device__ __forceinline__ uint32_t smem_u32(const void* p) {
    uint32_t a;
    asm("{ .reg .u64 t; cvta.to.shared.u64 t, %1; cvt.u32.u64 %0, t; }"
        : "=r"(a) : "l"(p));
    return a;
}

#define SWZ(o) ((o) ^ (((o) >> 3) & 0x70))

__device__ __forceinline__ void ldm4(uint32_t* r, uint32_t addr) {
    asm volatile("ldmatrix.sync.aligned.m8n8.x4.shared.b16 {%0,%1,%2,%3}, [%4];"
                 : "=r"(r[0]), "=r"(r[1]), "=r"(r[2]), "=r"(r[3]) : "r"(addr));
}
__device__ __forceinline__ void mma16816(float* c, const uint32_t* a,
                                         uint32_t b0, uint32_t b1) {
    asm volatile(
        "mma.sync.aligned.m16n8k16.row.col.f32.bf16.bf16.f32 "
        "{%0,%1,%2,%3}, {%4,%5,%6,%7}, {%8,%9}, {%0,%1,%2,%3};"
        : "+f"(c[0]), "+f"(c[1]), "+f"(c[2]), "+f"(c[3])
        : "r"(a[0]), "r"(a[1]), "r"(a[2]), "r"(a[3]), "r"(b0), "r"(b1));
}
__device__ __forceinline__ void cpa16(uint32_t dst, const void* src, int sz) {
    asm volatile("cp.async.cg.shared.global [%0], [%1], 16, %2;"
                 :: "r"(dst), "l"(src), "r"(sz));
}
#define CP_COMMIT() asm volatile("cp.async.commit_group;" ::: "memory")
#define CP_WAIT0()  asm volatile("cp.async.wait_group 0;" ::: "memory")

// ldmatrix x4 address, 128B pitch SW128
__device__ __forceinline__ uint32_t swaddr(uint32_t base, int row, int ks, int lane) {
    uint32_t o = (uint32_t)(row + (lane & 15)) * 128 + (uint32_t)ks * 32 +
                 (uint32_t)((lane >> 4) << 4);
    return base + SWZ(o);
}
__device__ __forceinline__ void split2(float a, float b, uint32_t& hi, uint32_t& lo) {
    bf16 ha = __float2bfloat16_rn(a), hb = __float2bfloat16_rn(b);
    bf16 la = __float2bfloat16_rn(a - __bfloat162float(ha));
    bf16 lb = __float2bfloat16_rn(b - __bfloat162float(hb));
    hi = (uint32_t)__bfloat16_as_ushort(ha) | ((uint32_t)__bfloat16_as_ushort(hb) << 16);
    lo = (uint32_t)__bfloat16_as_ushort(la) | ((uint32_t)__bfloat16_as_ushort(lb) << 16);
}

// ---------------------------------------------------------------------------
// Weight transpose + split: W[K][N] fp32 -> out_hi/lo[N][K] bf16
// ---------------------------------------------------------------------------
__global__ void convw(const float* __restrict__ W, bf16* __restrict__ hi,
                      bf16* __restrict__ lo, int K, int N)
{
    __shared__ float tile[32][33];
    int k0 = blockIdx.y * 32, n0 = blockIdx.x * 32;
    int tx = threadIdx.x, ty = threadIdx.y;
    #pragma unroll
    for (int i = ty; i < 32; i += 8)
        tile[i][tx] = W[(size_t)(k0 + i) * N + n0 + tx];
    __syncthreads();
    #pragma unroll
    for (int i = ty; i < 32; i += 8) {
        float v = tile[tx][i];
        bf16 h = __float2bfloat16_rn(v);
        size_t o = (size_t)(n0 + i) * K + k0 + tx;
        hi[o] = h;
        lo[o] = __float2bfloat16_rn(v - __bfloat162float(h));
    }
}

__global__ void mkbias(const float* __restrict__ bq, const float* __restrict__ bv,
                       float* __restrict__ out)
{
    int i = blockIdx.x * 256 + threadIdx.x;
    if (i >= NQKV) return;
    out[i] = (i < DM) ? bq[i] : (i < 2 * DM) ? 0.f : bv[i - 2 * DM];
}

// ---------------------------------------------------------------------------
// GEMM: C = epi(A @ B^T), A planes [M][K], B planes [N][K] (bf16 hi/lo)
//  mode 0: fp32 C = v + bias ; 1: gelu -> Chi/Clo ; 2: fp32 C = res+(v+bias)*lam
//  CTA 128x64, BK=64, 2-stage cp.async, 8 warps (32x32), 1 barrier/chunk,
//  fragment double-buffering over ks.
// ---------------------------------------------------------------------------
#define GSTAGE    49152
#define GEMM_SMEM (2 * GSTAGE)   // 96 KB -> 2 CTAs/SM

__global__ void __launch_bounds__(256, 2) mmagemm(
    const bf16* __restrict__ Ahi, const bf16* __restrict__ Alo,
    const bf16* __restrict__ Bhi, const bf16* __restrict__ Blo,
    const float* __restrict__ bias, const float* __restrict__ res,
    const float* __restrict__ lam, float* __restrict__ C,
    bf16* __restrict__ Chi, bf16* __restrict__ Clo,
    int M, int N, int K, int mode)
{
    extern __shared__ char smem[];
    uint32_t sb = smem_u32(smem);

    int t = threadIdx.x, wid = t >> 5, lane = t & 31;
    int bm = blockIdx.y * TM, bn = blockIdx.x * TN;

    int wm = wid >> 1, wn = wid & 1;       // 4 x 2 warps of 32x32
    int rmw = wm * 32, nbw = wn * 32;

    // A loaders: 4 chunks/thread; B loaders: 2 chunks/thread (16B chunks)
    int ar[4], bw_r[2];
    uint32_t adsw[4], bdsw[2];
    #pragma unroll
    for (int j = 0; j < 4; j++) {
        int ci = j * 256 + t;
        ar[j] = ci >> 3;
        adsw[j] = SWZ((uint32_t)(ar[j] * 128 + (ci & 7) * 16));
    }
    #pragma unroll
    for (int j = 0; j < 2; j++) {
        int ci = j * 256 + t;
        bw_r[j] = ci >> 3;
        bdsw[j] = SWZ((uint32_t)(bw_r[j] * 128 + (ci & 7) * 16));
    }

    float acc[2][4][4];
    #pragma unroll
    for (int i = 0; i < 2; i++)
        #pragma unroll
        for (int j = 0; j < 4; j++)
            #pragma unroll
            for (int r = 0; r < 4; r++) acc[i][j][r] = 0.f;

    const int nk = K / BK;

    auto prefetch = [&](int kchunk, int stage) {
        uint32_t s0 = sb + stage * GSTAGE;
        int kc = kchunk * BK;
        #pragma unroll
        for (int j = 0; j < 4; j++) {
            int ci = j * 256 + t;
            int va = (bm + ar[j]) < M ? 16 : 0;
            size_t ao = (size_t)(bm + ar[j]) * K + kc + (ci & 7) * 8;
            cpa16(s0 + adsw[j],         Ahi + ao, va);
            cpa16(s0 + 16384 + adsw[j], Alo + ao, va);
        }
        #pragma unroll
        for (int j = 0; j < 2; j++) {
            int ci = j * 256 + t;
            size_t bo = (size_t)(bn + bw_r[j]) * K + kc + (ci & 7) * 8;
            cpa16(s0 + 32768 + bdsw[j], Bhi + bo, 16);
            cpa16(s0 + 40960 + bdsw[j], Blo + bo, 16);
        }
        CP_COMMIT();
    };

    prefetch(0, 0);

    for (int ki = 0; ki < nk; ki++) {
        CP_WAIT0();
        __syncthreads();
        if (ki + 1 < nk) prefetch(ki + 1, (ki + 1) & 1);

        uint32_t sAh = sb + (ki & 1) * GSTAGE;
        uint32_t sAl = sAh + 16384, sBh = sAh + 32768, sBl = sAh + 40960;

        // fragment double buffers: B(hi,lo) + A-hi; A-lo single-buffered
        uint32_t bh[2][8], bl[2][8], ah[2][2][4], al[2][4];

        // preload ks=0 fragments
        #pragma unroll
        for (int j = 0; j < 2; j++) {
            ldm4(&bh[0][j * 4], swaddr(sBh, nbw + j * 16, 0, lane));
            ldm4(&bl[0][j * 4], swaddr(sBl, nbw + j * 16, 0, lane));
        }
        #pragma unroll
        for (int mi = 0; mi < 2; mi++)
            ldm4(ah[0][mi], swaddr(sAh, rmw + mi * 16, 0, lane));

        #pragma unroll
        for (int ks = 0; ks < 4; ks++) {
            int cur = ks & 1, nxt = cur ^ 1;

            // issue A-lo(ks) early so its latency hides under the hi MMAs
            #pragma unroll
            for (int mi = 0; mi < 2; mi++)
                ldm4(al[mi], swaddr(sAl, rmw + mi * 16, ks, lane));

            // hi*hi + hi*lo (24 MMAs)
            #pragma unroll
            for (int mi = 0; mi < 2; mi++)
                #pragma unroll
                for (int j2 = 0; j2 < 4; j2++) {
                    int base = (j2 >> 1) * 4, sel = j2 & 1;
                    mma16816(acc[mi][j2], ah[cur][mi],
                             bh[cur][base + sel], bh[cur][base + 2 + sel]);
                    mma16816(acc[mi][j2], ah[cur][mi],
                             bl[cur][base + sel], bl[cur][base + 2 + sel]);
                }

            // prefetch next ks fragments while lo*hi MMAs run
            if (ks < 3) {
                #pragma unroll
                for (int j = 0; j < 2; j++) {
                    ldm4(&bh[nxt][j * 4], swaddr(sBh, nbw + j * 16, ks + 1, lane));
                    ldm4(&bl[nxt][j * 4], swaddr(sBl, nbw + j * 16, ks + 1, lane));
                }
                #pragma unroll
                for (int mi = 0; mi < 2; mi++)
                    ldm4(ah[nxt][mi], swaddr(sAh, rmw + mi * 16, ks + 1, lane));
            }

            // lo*hi (8 MMAs)
            #pragma unroll
            for (int mi = 0; mi < 2; mi++)
                #pragma unroll
                for (int j2 = 0; j2 < 4; j2++) {
                    int base = (j2 >> 1) * 4, sel = j2 & 1;
                    mma16816(acc[mi][j2], al[mi],
                             bh[cur][base + sel], bh[cur][base + 2 + sel]);
                }
        }
    }

    // ---- epilogue ----
    int r0 = lane >> 2, c0 = (lane & 3) * 2;
    #pragma unroll
    for (int mi = 0; mi < 2; mi++) {
        #pragma unroll
        for (int j2 = 0; j2 < 4; j2++) {
            int gn = bn + nbw + j2 * 8 + c0;
            float b0 = 0.f, b1 = 0.f;
            if (bias) { b0 = bias[gn]; b1 = bias[gn + 1]; }
            float l0 = 0.f, l1 = 0.f;
            if (mode == 2) { l0 = lam[gn]; l1 = lam[gn + 1]; }
            #pragma unroll
            for (int half = 0; half < 2; half++) {
                int gm = bm + rmw + mi * 16 + r0 + half * 8;
                if (gm >= M) continue;
                float vx = acc[mi][j2][half * 2 + 0] + b0;
                float vy = acc[mi][j2][half * 2 + 1] + b1;
                if (mode == 1) {
                    vx = 0.5f * vx * (1.0f + erff(vx * 0.70710678118654752f));
                    vy = 0.5f * vy * (1.0f + erff(vy * 0.70710678118654752f));
                    uint32_t hi, lo;
                    split2(vx, vy, hi, lo);
                    size_t o = (size_t)gm * N + gn;
                    *(uint32_t*)(Chi + o) = hi;
                    *(uint32_t*)(Clo + o) = lo;
                } else {
                    if (mode == 2) {
                        const float2 rv = *(const float2*)(res + (size_t)gm * N + gn);
                        vx = rv.x + vx * l0;
                        vy = rv.y + vy * l1;
                    }
                    *(float2*)(C + (size_t)gm * N + gn) = make_float2(vx, vy);
                }
            }
        }
    }
}

// ---------------------------------------------------------------------------
// Patch embed
// ---------------------------------------------------------------------------
__global__ void embed_kernel(const float* __restrict__ x, const float* __restrict__ cls,
                             float* __restrict__ h)
{
    int i = blockIdx.x * 256 + threadIdx.x;
    if (i >= MROWS * DM) return;
    int c = i % DM;
    int s = (i / DM) % SEQ;
    int b = i / (DM * SEQ);
    h[i] = (s == 0) ? cls[c] : x[((size_t)(b * 196 + s - 1)) * DM + c];
}

// ---------------------------------------------------------------------------
// LayerNorm -> bf16 hi/lo planes
// ---------------------------------------------------------------------------
__global__ void ln_kernel(const float* __restrict__ x, const float* __restrict__ g,
                          const float* __restrict__ bta,
                          bf16* __restrict__ yhi, bf16* __restrict__ ylo)
{
    int row = blockIdx.x;
    const float* xr = x + (size_t)row * DM;
    int t = threadIdx.x;
    float v0 = xr[t], v1 = xr[t + 256], v2 = xr[t + 512];
    __shared__ float sh[8];

    float s = v0 + v1 + v2;
    #pragma unroll
    for (int o = 16; o; o >>= 1) s += __shfl_xor_sync(0xffffffffu, s, o);
    if ((t & 31) == 0) sh[t >> 5] = s;
    __syncthreads();
    if (t == 0) { float tot = 0.f; for (int i = 0; i < 8; i++) tot += sh[i]; sh[0] = tot; }
    __syncthreads();
    float mean = sh[0] * (1.0f / 768.0f);
    __syncthreads();

    float d0 = v0 - mean, d1 = v1 - mean, d2 = v2 - mean;
    s = d0 * d0 + d1 * d1 + d2 * d2;
    #pragma unroll
    for (int o = 16; o; o >>= 1) s += __shfl_xor_sync(0xffffffffu, s, o);
    if ((t & 31) == 0) sh[t >> 5] = s;
    __syncthreads();
    if (t == 0) { float tot = 0.f; for (int i = 0; i < 8; i++) tot += sh[i]; sh[0] = tot; }
    __syncthreads();
    float rstd = rsqrtf(sh[0] * (1.0f / 768.0f) + 1e-12f);

    size_t base = (size_t)row * DM;
    #pragma unroll
    for (int j = 0; j < 3; j++) {
        int col = t + j * 256;
        float d = (j == 0) ? d0 : (j == 1) ? d1 : d2;
        float v = d * rstd * g[col] + bta[col];
        bf16 h = __float2bfloat16_rn(v);
        yhi[base + col] = h;
        ylo[base + col] = __float2bfloat16_rn(v - __bfloat162float(h));
    }
}

// ---------------------------------------------------------------------------
// Attention: qkv fused input [M][2304]; rel column + row/col LUT in smem.
// ---------------------------------------------------------------------------
#define KS_PITCH 65
#define ATT_SMEM_FLOATS (2 * SEQ * KS_PITCH + 8 * 64 + 8 * 200 + NDREL + 2 * SEQ)
#define ATT_SMEM_BYTES  (ATT_SMEM_FLOATS * 4)

__global__ void attn_kernel(const float* __restrict__ qkv, const float* __restrict__ rel,
                            bf16* __restrict__ chi, bf16* __restrict__ clo)
{
    int h = blockIdx.x, b = blockIdx.y;
    extern __shared__ float sm[];
    float* Ks   = sm;
    float* Vs   = sm + SEQ * KS_PITCH;
    float* qs   = sm + 2 * SEQ * KS_PITCH;
    float* Ps   = qs + 8 * 64;
    float* rels = Ps + 8 * 200;
    int*   rw   = (int*)(rels + NDREL);
    int*   cl   = rw + SEQ;

    int t = threadIdx.x;
    for (int idx = t; idx < SEQ * HD; idx += 256) {
        int kk = idx >> 6, d = idx & 63;
        size_t g = (size_t)(b * SEQ + kk) * NQKV + h * HD + d;
        Ks[kk * KS_PITCH + d] = qkv[g + DM];
        Vs[kk * KS_PITCH + d] = qkv[g + 2 * DM];
    }
    for (int idx = t; idx < NDREL; idx += 256)
        rels[idx] = rel[idx * NH + h];
    for (int idx = t; idx < SEQ; idx += 256) {
        rw[idx] = (idx > 0) ? (idx - 1) / 14 : 0;
        cl[idx] = (idx > 0) ? (idx - 1) % 14 : 0;
    }
    __syncthreads();

    int w = t >> 5, lane = t & 31;
    for (int q = w; q < SEQ; q += 8) {
        size_t qbase = (size_t)(b * SEQ + q) * NQKV + h * HD;
        qs[w * 64 + lane]      = qkv[qbase + lane];
        qs[w * 64 + lane + 32] = qkv[qbase + lane + 32];
        __syncwarp();

        int rwq = rw[q], clq = cl[q];
        bool isq0 = (q == 0);

        float s[7];
        float mx = -1e30f;
        #pragma unroll
        for (int j = 0; j < 7; j++) {
            int kk = lane + j * 32;
            float acc = -1e30f;
            if (kk < SEQ) {
                float v = 0.f;
                #pragma unroll
                for (int d = 0; d < HD; d++) v += qs[w * 64 + d] * Ks[kk * KS_PITCH + d];
                float bias;
                if (isq0)          bias = rels[(kk == 0) ? NDREL - 1 : NDREL - 3];
                else if (kk == 0)  bias = rels[NDREL - 2];
                else               bias = rels[(rwq - rw[kk] + 13) * 27 +
                                               (clq - cl[kk] + 13)];
                acc = v * 0.125f + bias;
            }
            s[j] = acc;
            mx = fmaxf(mx, acc);
        }
        #pragma unroll
        for (int o = 16; o; o >>= 1) mx = fmaxf(mx, __shfl_xor_sync(0xffffffffu, mx, o));

        float sum = 0.f;
        #pragma unroll
        for (int j = 0; j < 7; j++) {
            int kk = lane + j * 32;
            float e = (kk < SEQ) ? expf(s[j] - mx) : 0.f;
            s[j] = e;
            sum += e;
        }
        #pragma unroll
        for (int o = 16; o; o >>= 1) sum += __shfl_xor_sync(0xffffffffu, sum, o);
        float inv = 1.0f / sum;

        #pragma unroll
        for (int j = 0; j < 7; j++) {
            int kk = lane + j * 32;
            if (kk < SEQ) Ps[w * 200 + kk] = s[j] * inv;
        }
        __syncwarp();

        float a0 = 0.f, a1 = 0.f;
        for (int kk = 0; kk < SEQ; kk++) {
            float p = Ps[w * 200 + kk];
            a0 += p * Vs[kk * KS_PITCH + lane];
            a1 += p * Vs[kk * KS_PITCH + lane + 32];
        }
        size_t cbase = (size_t)(b * SEQ + q) * DM + h * HD;
        bf16 h0 = __float2bfloat16_rn(a0);
        bf16 h1 = __float2bfloat16_rn(a1);
        chi[cbase + lane]      = h0;
        chi[cbase + lane + 32] = h1;
        clo[cbase + lane]      = __float2bfloat16_rn(a0 - __bfloat162float(h0));
        clo[cbase + lane + 32] = __float2bfloat16_rn(a1 - __bfloat162float(h1));
        __syncwarp();
    }
}

// ---------------------------------------------------------------------------
// Orchestration
// ---------------------------------------------------------------------------
extern "C" void kernel_launch(void* const* d_in, const int* in_sizes, int n_in,
                              void* d_out, int out_size)
{
    const float* x    = (const float*)d_in[0];
    const float* cls  = (const float*)d_in[1];
    const float* g1   = (const float*)d_in[2];
    const float* b1   = (const float*)d_in[3];
    const float* Wq   = (const float*)d_in[4];
    const float* bq   = (const float*)d_in[5];
    const float* Wk   = (const float*)d_in[6];
    const float* Wv   = (const float*)d_in[7];
    const float* bv   = (const float*)d_in[8];
    const float* rel  = (const float*)d_in[9];
    const float* Wo   = (const float*)d_in[10];
    const float* bo   = (const float*)d_in[11];
    const float* lam1 = (const float*)d_in[12];
    const float* g2   = (const float*)d_in[13];
    const float* b2   = (const float*)d_in[14];
    const float* Wi   = (const float*)d_in[15];
    const float* bi   = (const float*)d_in[16];
    const float* Wmo  = (const float*)d_in[17];
    const float* bmo  = (const float*)d_in[18];
    const float* lam2 = (const float*)d_in[19];

    float *h, *qkv, *bqkv;
    bf16 *hnh, *hnl, *cth, *ctl, *fh, *fl;
    bf16 *wqh, *wql, *woh, *wol, *wih, *wil, *wmh, *wml;
    cudaGetSymbolAddress((void**)&h,    g_h);
    cudaGetSymbolAddress((void**)&qkv,  g_qkv);
    cudaGetSymbolAddress((void**)&bqkv, g_bqkv);
    cudaGetSymbolAddress((void**)&hnh,  g_hn_hi);
    cudaGetSymbolAddress((void**)&hnl,  g_hn_lo);
    cudaGetSymbolAddress((void**)&cth,  g_ctx_hi);
    cudaGetSymbolAddress((void**)&ctl,  g_ctx_lo);
    cudaGetSymbolAddress((void**)&fh,   g_f_hi);
    cudaGetSymbolAddress((void**)&fl,   g_f_lo);
    cudaGetSymbolAddress((void**)&wqh,  g_wqkv_hi);
    cudaGetSymbolAddress((void**)&wql,  g_wqkv_lo);
    cudaGetSymbolAddress((void**)&woh,  g_wo_hi);
    cudaGetSymbolAddress((void**)&wol,  g_wo_lo);
    cudaGetSymbolAddress((void**)&wih,  g_wi_hi);
    cudaGetSymbolAddress((void**)&wil,  g_wi_lo);
    cudaGetSymbolAddress((void**)&wmh,  g_wmo_hi);
    cudaGetSymbolAddress((void**)&wml,  g_wmo_lo);

    cudaFuncSetAttribute(attn_kernel, cudaFuncAttributeMaxDynamicSharedMemorySize,
                         ATT_SMEM_BYTES);
    cudaFuncSetAttribute(mmagemm, cudaFuncAttributeMaxDynamicSharedMemorySize,
                         GEMM_SMEM);

    dim3 cb(32, 8);
    for (int l = 0; l < 3; l++) {
        size_t wo  = (size_t)l * DM * DM;
        size_t wio = (size_t)l * DM * DF;
        bf16* qh = wqh + (size_t)l * NQKV * DM;
        bf16* ql = wql + (size_t)l * NQKV * DM;
        convw<<<dim3(DM / 32, DM / 32), cb>>>(Wq + wo, qh,               ql,               DM, DM);
        convw<<<dim3(DM / 32, DM / 32), cb>>>(Wk + wo, qh + DM * DM,     ql + DM * DM,     DM, DM);
        convw<<<dim3(DM / 32, DM / 32), cb>>>(Wv + wo, qh + 2 * DM * DM, ql + 2 * DM * DM, DM, DM);
        convw<<<dim3(DM / 32, DM / 32), cb>>>(Wo + wo, woh + wo, wol + wo, DM, DM);
        convw<<<dim3(DF / 32, DM / 32), cb>>>(Wi + wio, wih + (size_t)l * DF * DM,
                                              wil + (size_t)l * DF * DM, DM, DF);
        convw<<<dim3(DM / 32, DF / 32), cb>>>(Wmo + wio, wmh + (size_t)l * DM * DF,
                                              wml + (size_t)l * DM * DF, DF, DM);
    }

    embed_kernel<<<(MROWS * DM + 255) / 256, 256>>>(x, cls, h);

    int mt = (MROWS + TM - 1) / TM;        // 99
    dim3 gqkv(NQKV / TN, mt);              // (36, 99)
    dim3 g768(DM / TN, mt);                // (12, 99)
    dim3 g3072(DF / TN, mt);               // (48, 99)

    for (int l = 0; l < 3; l++) {
        bf16* qh = wqh + (size_t)l * NQKV * DM;
        bf16* ql = wql + (size_t)l * NQKV * DM;
        bf16* oh = woh + (size_t)l * DM * DM;
        bf16* ol = wol + (size_t)l * DM * DM;
        bf16* ih = wih + (size_t)l * DF * DM;
        bf16* il = wil + (size_t)l * DF * DM;
        bf16* mh = wmh + (size_t)l * DM * DF;
        bf16* ml = wml + (size_t)l * DM * DF;

        mkbias<<<(NQKV + 255) / 256, 256>>>(bq + l * DM, bv + l * DM, bqkv);

        ln_kernel<<<MROWS, 256>>>(h, g1 + l * DM, b1 + l * DM, hnh, hnl);

        mmagemm<<<gqkv, 256, GEMM_SMEM>>>(hnh, hnl, qh, ql, bqkv,
                                          nullptr, nullptr, qkv, nullptr, nullptr,
                                          MROWS, NQKV, DM, 0);

        attn_kernel<<<dim3(NH, NB), 256, ATT_SMEM_BYTES>>>(
            qkv, rel + (size_t)l * NDREL * NH, cth, ctl);

        mmagemm<<<g768, 256, GEMM_SMEM>>>(cth, ctl, oh, ol, bo + l * DM,
                                          h, lam1 + l * DM, h, nullptr, nullptr,
                                          MROWS, DM, DM, 2);

        ln_kernel<<<MROWS, 256>>>(h, g2 + l * DM, b2 + l * DM, hnh, hnl);

        mmagemm<<<g3072, 256, GEMM_SMEM>>>(hnh, hnl, ih, il, bi + l * DF,
                                           nullptr, nullptr, nullptr, fh, fl,
                                           MROWS, DF, DM, 1);

        mmagemm<<<g768, 256, GEMM_SMEM>>>(fh, fl, mh, ml, bmo + l * DM,
                                          h, lam2 + l * DM,
                                          (l == 2) ? (float*)d_out : h, nullptr, nullptr,
                                          MROWS, DM, DF, 2);
    }
}

// round 12
// speedup vs baseline: 1.0283x; 1.0283x over previous
#include <cuda_runtime.h>
#include <cuda_bf16.h>
#include <math.h>
#include <stdint.h>

// ---------------------------------------------------------------------------
// BEiT encoder: B=64, S=197, DM=768, H=12, D=64, DF=3072, L=3
// GEMMs: mma.sync bf16 hi/lo split, 2-stage cp.async (BK=64), SW128,
// 128x64 CTA tile, 2 CTAs/SM, ONE barrier/chunk (R8 config).
// Attention: float2-interleaved V rows FIRST in smem (8B alignment), unrolled P.V.
// ---------------------------------------------------------------------------

#define MROWS 12608
#define DM    768
#define DF    3072
#define NQKV  2304
#define SEQ   197
#define NB    64
#define NH    12
#define HD    64
#define NDREL 732

#define TM 128
#define TN 64
#define BK 64

typedef __nv_bfloat16 bf16;

// fp32 scratch
__device__ float g_h   [MROWS * DM];
__device__ float g_qkv [MROWS * NQKV];
__device__ float g_bqkv[NQKV];
// bf16 hi/lo activation planes
__device__ bf16 g_hn_hi [MROWS * DM];
__device__ bf16 g_hn_lo [MROWS * DM];
__device__ bf16 g_ctx_hi[MROWS * DM];
__device__ bf16 g_ctx_lo[MROWS * DM];
__device__ bf16 g_f_hi  [MROWS * DF];
__device__ bf16 g_f_lo  [MROWS * DF];
// transposed weight planes [N][K]
__device__ bf16 g_wqkv_hi[3 * NQKV * DM];
__device__ bf16 g_wqkv_lo[3 * NQKV * DM];
__device__ bf16 g_wo_hi  [3 * DM * DM];
__device__ bf16 g_wo_lo  [3 * DM * DM];
__device__ bf16 g_wi_hi  [3 * DF * DM];
__device__ bf16 g_wi_lo  [3 * DF * DM];
__device__ bf16 g_wmo_hi [3 * DM * DF];
__device__ bf16 g_wmo_lo [3 * DM * DF];

// ---------------------------------------------------------------------------
// helpers
// ---------------------------------------------------------------------------
__device__ __forceinline__ uint32_t smem_u32(const void* p) {
    uint32_t a;
    asm("{ .reg .u64 t; cvta.to.shared.u64 t, %1; cvt.u32.u64 %0, t; }"
        : "=r"(a) : "l"(p));
    return a;
}

#define SWZ(o) ((o) ^ (((o) >> 3) & 0x70))

__device__ __forceinline__ void ldm4(uint32_t* r, uint32_t addr) {
    asm volatile("ldmatrix.sync.aligned.m8n8.x4.shared.b16 {%0,%1,%2,%3}, [%4];"
                 : "=r"(r[0]), "=r"(r[1]), "=r"(r[2]), "=r"(r[3]) : "r"(addr));
}
__device__ __forceinline__ void mma16816(float* c, const uint32_t* a,
                                         uint32_t b0, uint32_t b1) {
    asm volatile(
        "mma.sync.aligned.m16n8k16.row.col.f32.bf16.bf16.f32 "
        "{%0,%1,%2,%3}, {%4,%5,%6,%7}, {%8,%9}, {%0,%1,%2,%3};"
        : "+f"(c[0]), "+f"(c[1]), "+f"(c[2]), "+f"(c[3])
        : "r"(a[0]), "r"(a[1]), "r"(a[2]), "r"(a[3]), "r"(b0), "r"(b1));
}
__device__ __forceinline__ void cpa16(uint32_t dst, const void* src, int sz) {
    asm volatile("cp.async.cg.shared.global [%0], [%1], 16, %2;"
                 :: "r"(dst), "l"(src), "r"(sz));
}
#define CP_COMMIT() asm volatile("cp.async.commit_group;" ::: "memory")
#define CP_WAIT0()  asm volatile("cp.async.wait_group 0;" ::: "memory")

// ldmatrix x4 address, 128B pitch SW128
__device__ __forceinline__ uint32_t swaddr(uint32_t base, int row, int ks, int lane) {
    uint32_t o = (uint32_t)(row + (lane & 15)) * 128 + (uint32_t)ks * 32 +
                 (uint32_t)((lane >> 4) << 4);
    return base + SWZ(o);
}
__device__ __forceinline__ void split2(float a, float b, uint32_t& hi, uint32_t& lo) {
    bf16 ha = __float2bfloat16_rn(a), hb = __float2bfloat16_rn(b);
    bf16 la = __float2bfloat16_rn(a - __bfloat162float(ha));
    bf16 lb = __float2bfloat16_rn(b - __bfloat162float(hb));
    hi = (uint32_t)__bfloat16_as_ushort(ha) | ((uint32_t)__bfloat16_as_ushort(hb) << 16);
    lo = (uint32_t)__bfloat16_as_ushort(la) | ((uint32_t)__bfloat16_as_ushort(lb) << 16);
}

// ---------------------------------------------------------------------------
// Weight transpose + split: W[K][N] fp32 -> out_hi/lo[N][K] bf16
// ---------------------------------------------------------------------------
__global__ void convw(const float* __restrict__ W, bf16* __restrict__ hi,
                      bf16* __restrict__ lo, int K, int N)
{
    __shared__ float tile[32][33];
    int k0 = blockIdx.y * 32, n0 = blockIdx.x * 32;
    int tx = threadIdx.x, ty = threadIdx.y;
    #pragma unroll
    for (int i = ty; i < 32; i += 8)
        tile[i][tx] = W[(size_t)(k0 + i) * N + n0 + tx];
    __syncthreads();
    #pragma unroll
    for (int i = ty; i < 32; i += 8) {
        float v = tile[tx][i];
        bf16 h = __float2bfloat16_rn(v);
        size_t o = (size_t)(n0 + i) * K + k0 + tx;
        hi[o] = h;
        lo[o] = __float2bfloat16_rn(v - __bfloat162float(h));
    }
}

__global__ void mkbias(const float* __restrict__ bq, const float* __restrict__ bv,
                       float* __restrict__ out)
{
    int i = blockIdx.x * 256 + threadIdx.x;
    if (i >= NQKV) return;
    out[i] = (i < DM) ? bq[i] : (i < 2 * DM) ? 0.f : bv[i - 2 * DM];
}

// ---------------------------------------------------------------------------
// GEMM (R8 config): C = epi(A @ B^T), bf16 hi/lo planes.
//  mode 0: fp32 C = v + bias ; 1: gelu -> Chi/Clo ; 2: fp32 C = res+(v+bias)*lam
// ---------------------------------------------------------------------------
#define GSTAGE    49152
#define GEMM_SMEM (2 * GSTAGE)   // 96 KB -> 2 CTAs/SM

__global__ void __launch_bounds__(256, 2) mmagemm(
    const bf16* __restrict__ Ahi, const bf16* __restrict__ Alo,
    const bf16* __restrict__ Bhi, const bf16* __restrict__ Blo,
    const float* __restrict__ bias, const float* __restrict__ res,
    const float* __restrict__ lam, float* __restrict__ C,
    bf16* __restrict__ Chi, bf16* __restrict__ Clo,
    int M, int N, int K, int mode)
{
    extern __shared__ char smem[];
    uint32_t sb = smem_u32(smem);

    int t = threadIdx.x, wid = t >> 5, lane = t & 31;
    int bm = blockIdx.y * TM, bn = blockIdx.x * TN;

    int wm = wid >> 1, wn = wid & 1;       // 4 x 2 warps of 32x32
    int rmw = wm * 32, nbw = wn * 32;

    int ar[4], bw_r[2];
    uint32_t adsw[4], bdsw[2];
    #pragma unroll
    for (int j = 0; j < 4; j++) {
        int ci = j * 256 + t;
        ar[j] = ci >> 3;
        adsw[j] = SWZ((uint32_t)(ar[j] * 128 + (ci & 7) * 16));
    }
    #pragma unroll
    for (int j = 0; j < 2; j++) {
        int ci = j * 256 + t;
        bw_r[j] = ci >> 3;
        bdsw[j] = SWZ((uint32_t)(bw_r[j] * 128 + (ci & 7) * 16));
    }

    float acc[2][4][4];
    #pragma unroll
    for (int i = 0; i < 2; i++)
        #pragma unroll
        for (int j = 0; j < 4; j++)
            #pragma unroll
            for (int r = 0; r < 4; r++) acc[i][j][r] = 0.f;

    const int nk = K / BK;

    auto prefetch = [&](int kchunk, int stage) {
        uint32_t s0 = sb + stage * GSTAGE;
        int kc = kchunk * BK;
        #pragma unroll
        for (int j = 0; j < 4; j++) {
            int ci = j * 256 + t;
            int va = (bm + ar[j]) < M ? 16 : 0;
            size_t ao = (size_t)(bm + ar[j]) * K + kc + (ci & 7) * 8;
            cpa16(s0 + adsw[j],         Ahi + ao, va);
            cpa16(s0 + 16384 + adsw[j], Alo + ao, va);
        }
        #pragma unroll
        for (int j = 0; j < 2; j++) {
            int ci = j * 256 + t;
            size_t bo = (size_t)(bn + bw_r[j]) * K + kc + (ci & 7) * 8;
            cpa16(s0 + 32768 + bdsw[j], Bhi + bo, 16);
            cpa16(s0 + 40960 + bdsw[j], Blo + bo, 16);
        }
        CP_COMMIT();
    };

    prefetch(0, 0);

    for (int ki = 0; ki < nk; ki++) {
        CP_WAIT0();
        __syncthreads();
        if (ki + 1 < nk) prefetch(ki + 1, (ki + 1) & 1);

        uint32_t sAh = sb + (ki & 1) * GSTAGE;
        uint32_t sAl = sAh + 16384, sBh = sAh + 32768, sBl = sAh + 40960;

        #pragma unroll
        for (int ks = 0; ks < 4; ks++) {
            uint32_t bh[8], bl[8], a4[2][4];
            #pragma unroll
            for (int j = 0; j < 2; j++) {
                ldm4(&bh[j * 4], swaddr(sBh, nbw + j * 16, ks, lane));
                ldm4(&bl[j * 4], swaddr(sBl, nbw + j * 16, ks, lane));
            }
            #pragma unroll
            for (int mi = 0; mi < 2; mi++)
                ldm4(a4[mi], swaddr(sAh, rmw + mi * 16, ks, lane));
            #pragma unroll
            for (int mi = 0; mi < 2; mi++)
                #pragma unroll
                for (int j2 = 0; j2 < 4; j2++) {
                    int base = (j2 >> 1) * 4, sel = j2 & 1;
                    mma16816(acc[mi][j2], a4[mi], bh[base + sel], bh[base + 2 + sel]);
                    mma16816(acc[mi][j2], a4[mi], bl[base + sel], bl[base + 2 + sel]);
                }
            #pragma unroll
            for (int mi = 0; mi < 2; mi++)
                ldm4(a4[mi], swaddr(sAl, rmw + mi * 16, ks, lane));
            #pragma unroll
            for (int mi = 0; mi < 2; mi++)
                #pragma unroll
                for (int j2 = 0; j2 < 4; j2++) {
                    int base = (j2 >> 1) * 4, sel = j2 & 1;
                    mma16816(acc[mi][j2], a4[mi], bh[base + sel], bh[base + 2 + sel]);
                }
        }
    }

    // ---- epilogue ----
    int r0 = lane >> 2, c0 = (lane & 3) * 2;
    #pragma unroll
    for (int mi = 0; mi < 2; mi++) {
        #pragma unroll
        for (int j2 = 0; j2 < 4; j2++) {
            int gn = bn + nbw + j2 * 8 + c0;
            float b0 = 0.f, b1 = 0.f;
            if (bias) { b0 = bias[gn]; b1 = bias[gn + 1]; }
            float l0 = 0.f, l1 = 0.f;
            if (mode == 2) { l0 = lam[gn]; l1 = lam[gn + 1]; }
            #pragma unroll
            for (int half = 0; half < 2; half++) {
                int gm = bm + rmw + mi * 16 + r0 + half * 8;
                if (gm >= M) continue;
                float vx = acc[mi][j2][half * 2 + 0] + b0;
                float vy = acc[mi][j2][half * 2 + 1] + b1;
                if (mode == 1) {
                    vx = 0.5f * vx * (1.0f + erff(vx * 0.70710678118654752f));
                    vy = 0.5f * vy * (1.0f + erff(vy * 0.70710678118654752f));
                    uint32_t hi, lo;
                    split2(vx, vy, hi, lo);
                    size_t o = (size_t)gm * N + gn;
                    *(uint32_t*)(Chi + o) = hi;
                    *(uint32_t*)(Clo + o) = lo;
                } else {
                    if (mode == 2) {
                        const float2 rv = *(const float2*)(res + (size_t)gm * N + gn);
                        vx = rv.x + vx * l0;
                        vy = rv.y + vy * l1;
                    }
                    *(float2*)(C + (size_t)gm * N + gn) = make_float2(vx, vy);
                }
            }
        }
    }
}

// ---------------------------------------------------------------------------
// Patch embed
// ---------------------------------------------------------------------------
__global__ void embed_kernel(const float* __restrict__ x, const float* __restrict__ cls,
                             float* __restrict__ h)
{
    int i = blockIdx.x * 256 + threadIdx.x;
    if (i >= MROWS * DM) return;
    int c = i % DM;
    int s = (i / DM) % SEQ;
    int b = i / (DM * SEQ);
    h[i] = (s == 0) ? cls[c] : x[((size_t)(b * 196 + s - 1)) * DM + c];
}

// ---------------------------------------------------------------------------
// LayerNorm -> bf16 hi/lo planes
// ---------------------------------------------------------------------------
__global__ void ln_kernel(const float* __restrict__ x, const float* __restrict__ g,
                          const float* __restrict__ bta,
                          bf16* __restrict__ yhi, bf16* __restrict__ ylo)
{
    int row = blockIdx.x;
    const float* xr = x + (size_t)row * DM;
    int t = threadIdx.x;
    float v0 = xr[t], v1 = xr[t + 256], v2 = xr[t + 512];
    __shared__ float sh[8];

    float s = v0 + v1 + v2;
    #pragma unroll
    for (int o = 16; o; o >>= 1) s += __shfl_xor_sync(0xffffffffu, s, o);
    if ((t & 31) == 0) sh[t >> 5] = s;
    __syncthreads();
    if (t == 0) { float tot = 0.f; for (int i = 0; i < 8; i++) tot += sh[i]; sh[0] = tot; }
    __syncthreads();
    float mean = sh[0] * (1.0f / 768.0f);
    __syncthreads();

    float d0 = v0 - mean, d1 = v1 - mean, d2 = v2 - mean;
    s = d0 * d0 + d1 * d1 + d2 * d2;
    #pragma unroll
    for (int o = 16; o; o >>= 1) s += __shfl_xor_sync(0xffffffffu, s, o);
    if ((t & 31) == 0) sh[t >> 5] = s;
    __syncthreads();
    if (t == 0) { float tot = 0.f; for (int i = 0; i < 8; i++) tot += sh[i]; sh[0] = tot; }
    __syncthreads();
    float rstd = rsqrtf(sh[0] * (1.0f / 768.0f) + 1e-12f);

    size_t base = (size_t)row * DM;
    #pragma unroll
    for (int j = 0; j < 3; j++) {
        int col = t + j * 256;
        float d = (j == 0) ? d0 : (j == 1) ? d1 : d2;
        float v = d * rstd * g[col] + bta[col];
        bf16 h = __float2bfloat16_rn(v);
        yhi[base + col] = h;
        ylo[base + col] = __float2bfloat16_rn(v - __bfloat162float(h));
    }
}

// ---------------------------------------------------------------------------
// Attention: Vs2 (float2) FIRST in smem for 8B alignment.
// ---------------------------------------------------------------------------
#define KS_PITCH 65
#define VPITCH2  33   // float2 pitch per key row (32 pairs + 1 pad)
#define ATT_SMEM_FLOATS (SEQ * 2 * VPITCH2 + SEQ * KS_PITCH + 8 * 64 + 8 * 200 \
                         + NDREL + 2 * SEQ)
#define ATT_SMEM_BYTES  (ATT_SMEM_FLOATS * 4)

__global__ void attn_kernel(const float* __restrict__ qkv, const float* __restrict__ rel,
                            bf16* __restrict__ chi, bf16* __restrict__ clo)
{
    int h = blockIdx.x, b = blockIdx.y;
    extern __shared__ float sm[];
    float2* Vs2  = (float2*)sm;                          // [SEQ][VPITCH2], 16B-aligned base
    float*  Ks   = sm + SEQ * 2 * VPITCH2;               // 13002 floats (52008 B, 8B-mult)
    float*  qs   = Ks + SEQ * KS_PITCH;
    float*  Ps   = qs + 8 * 64;
    float*  rels = Ps + 8 * 200;
    int*    rw   = (int*)(rels + NDREL);
    int*    cl   = rw + SEQ;

    int t = threadIdx.x;
    for (int idx = t; idx < SEQ * HD; idx += 256) {
        int kk = idx >> 6, d = idx & 63;
        size_t g = (size_t)(b * SEQ + kk) * NQKV + h * HD + d;
        Ks[kk * KS_PITCH + d] = qkv[g + DM];
        // V interleaved: pair (d&31) holds (v[d<32], v[d>=32])
        ((float*)Vs2)[kk * 2 * VPITCH2 + (d & 31) * 2 + (d >> 5)] = qkv[g + 2 * DM];
    }
    for (int idx = t; idx < NDREL; idx += 256)
        rels[idx] = rel[idx * NH + h];
    for (int idx = t; idx < SEQ; idx += 256) {
        rw[idx] = (idx > 0) ? (idx - 1) / 14 : 0;
        cl[idx] = (idx > 0) ? (idx - 1) % 14 : 0;
    }
    __syncthreads();

    int w = t >> 5, lane = t & 31;
    for (int q = w; q < SEQ; q += 8) {
        size_t qbase = (size_t)(b * SEQ + q) * NQKV + h * HD;
        qs[w * 64 + lane]      = qkv[qbase + lane];
        qs[w * 64 + lane + 32] = qkv[qbase + lane + 32];
        __syncwarp();

        int rwq = rw[q], clq = cl[q];
        bool isq0 = (q == 0);

        float s[7];
        float mx = -1e30f;
        #pragma unroll
        for (int j = 0; j < 7; j++) {
            int kk = lane + j * 32;
            float acc = -1e30f;
            if (kk < SEQ) {
                float v = 0.f;
                #pragma unroll
                for (int d = 0; d < HD; d++) v += qs[w * 64 + d] * Ks[kk * KS_PITCH + d];
                float bias;
                if (isq0)          bias = rels[(kk == 0) ? NDREL - 1 : NDREL - 3];
                else if (kk == 0)  bias = rels[NDREL - 2];
                else               bias = rels[(rwq - rw[kk] + 13) * 27 +
                                               (clq - cl[kk] + 13)];
                acc = v * 0.125f + bias;
            }
            s[j] = acc;
            mx = fmaxf(mx, acc);
        }
        #pragma unroll
        for (int o = 16; o; o >>= 1) mx = fmaxf(mx, __shfl_xor_sync(0xffffffffu, mx, o));

        float sum = 0.f;
        #pragma unroll
        for (int j = 0; j < 7; j++) {
            int kk = lane + j * 32;
            float e = (kk < SEQ) ? expf(s[j] - mx) : 0.f;
            s[j] = e;
            sum += e;
        }
        #pragma unroll
        for (int o = 16; o; o >>= 1) sum += __shfl_xor_sync(0xffffffffu, sum, o);
        float inv = 1.0f / sum;

        #pragma unroll
        for (int j = 0; j < 7; j++) {
            int kk = lane + j * 32;
            if (kk < SEQ) Ps[w * 200 + kk] = s[j] * inv;
        }
        __syncwarp();

        float a0 = 0.f, a1 = 0.f;
        {
            const float* pw = Ps + w * 200;
            #pragma unroll 4
            for (int kk = 0; kk < SEQ - 1; kk++) {
                float  p = pw[kk];
                float2 v = Vs2[kk * VPITCH2 + lane];
                a0 += p * v.x;
                a1 += p * v.y;
            }
            float  p = pw[SEQ - 1];
            float2 v = Vs2[(SEQ - 1) * VPITCH2 + lane];
            a0 += p * v.x;
            a1 += p * v.y;
        }
        size_t cbase = (size_t)(b * SEQ + q) * DM + h * HD;
        bf16 h0 = __float2bfloat16_rn(a0);
        bf16 h1 = __float2bfloat16_rn(a1);
        chi[cbase + lane]      = h0;
        chi[cbase + lane + 32] = h1;
        clo[cbase + lane]      = __float2bfloat16_rn(a0 - __bfloat162float(h0));
        clo[cbase + lane + 32] = __float2bfloat16_rn(a1 - __bfloat162float(h1));
        __syncwarp();
    }
}

// ---------------------------------------------------------------------------
// Orchestration
// ---------------------------------------------------------------------------
extern "C" void kernel_launch(void* const* d_in, const int* in_sizes, int n_in,
                              void* d_out, int out_size)
{
    const float* x    = (const float*)d_in[0];
    const float* cls  = (const float*)d_in[1];
    const float* g1   = (const float*)d_in[2];
    const float* b1   = (const float*)d_in[3];
    const float* Wq   = (const float*)d_in[4];
    const float* bq   = (const float*)d_in[5];
    const float* Wk   = (const float*)d_in[6];
    const float* Wv   = (const float*)d_in[7];
    const float* bv   = (const float*)d_in[8];
    const float* rel  = (const float*)d_in[9];
    const float* Wo   = (const float*)d_in[10];
    const float* bo   = (const float*)d_in[11];
    const float* lam1 = (const float*)d_in[12];
    const float* g2   = (const float*)d_in[13];
    const float* b2   = (const float*)d_in[14];
    const float* Wi   = (const float*)d_in[15];
    const float* bi   = (const float*)d_in[16];
    const float* Wmo  = (const float*)d_in[17];
    const float* bmo  = (const float*)d_in[18];
    const float* lam2 = (const float*)d_in[19];

    float *h, *qkv, *bqkv;
    bf16 *hnh, *hnl, *cth, *ctl, *fh, *fl;
    bf16 *wqh, *wql, *woh, *wol, *wih, *wil, *wmh, *wml;
    cudaGetSymbolAddress((void**)&h,    g_h);
    cudaGetSymbolAddress((void**)&qkv,  g_qkv);
    cudaGetSymbolAddress((void**)&bqkv, g_bqkv);
    cudaGetSymbolAddress((void**)&hnh,  g_hn_hi);
    cudaGetSymbolAddress((void**)&hnl,  g_hn_lo);
    cudaGetSymbolAddress((void**)&cth,  g_ctx_hi);
    cudaGetSymbolAddress((void**)&ctl,  g_ctx_lo);
    cudaGetSymbolAddress((void**)&fh,   g_f_hi);
    cudaGetSymbolAddress((void**)&fl,   g_f_lo);
    cudaGetSymbolAddress((void**)&wqh,  g_wqkv_hi);
    cudaGetSymbolAddress((void**)&wql,  g_wqkv_lo);
    cudaGetSymbolAddress((void**)&woh,  g_wo_hi);
    cudaGetSymbolAddress((void**)&wol,  g_wo_lo);
    cudaGetSymbolAddress((void**)&wih,  g_wi_hi);
    cudaGetSymbolAddress((void**)&wil,  g_wi_lo);
    cudaGetSymbolAddress((void**)&wmh,  g_wmo_hi);
    cudaGetSymbolAddress((void**)&wml,  g_wmo_lo);

    cudaFuncSetAttribute(attn_kernel, cudaFuncAttributeMaxDynamicSharedMemorySize,
                         ATT_SMEM_BYTES);
    cudaFuncSetAttribute(mmagemm, cudaFuncAttributeMaxDynamicSharedMemorySize,
                         GEMM_SMEM);

    dim3 cb(32, 8);
    for (int l = 0; l < 3; l++) {
        size_t wo  = (size_t)l * DM * DM;
        size_t wio = (size_t)l * DM * DF;
        bf16* qh = wqh + (size_t)l * NQKV * DM;
        bf16* ql = wql + (size_t)l * NQKV * DM;
        convw<<<dim3(DM / 32, DM / 32), cb>>>(Wq + wo, qh,               ql,               DM, DM);
        convw<<<dim3(DM / 32, DM / 32), cb>>>(Wk + wo, qh + DM * DM,     ql + DM * DM,     DM, DM);
        convw<<<dim3(DM / 32, DM / 32), cb>>>(Wv + wo, qh + 2 * DM * DM, ql + 2 * DM * DM, DM, DM);
        convw<<<dim3(DM / 32, DM / 32), cb>>>(Wo + wo, woh + wo, wol + wo, DM, DM);
        convw<<<dim3(DF / 32, DM / 32), cb>>>(Wi + wio, wih + (size_t)l * DF * DM,
                                              wil + (size_t)l * DF * DM, DM, DF);
        convw<<<dim3(DM / 32, DF / 32), cb>>>(Wmo + wio, wmh + (size_t)l * DM * DF,
                                              wml + (size_t)l * DM * DF, DF, DM);
    }

    embed_kernel<<<(MROWS * DM + 255) / 256, 256>>>(x, cls, h);

    int mt = (MROWS + TM - 1) / TM;        // 99
    dim3 gqkv(NQKV / TN, mt);              // (36, 99)
    dim3 g768(DM / TN, mt);                // (12, 99)
    dim3 g3072(DF / TN, mt);               // (48, 99)

    for (int l = 0; l < 3; l++) {
        bf16* qh = wqh + (size_t)l * NQKV * DM;
        bf16* ql = wql + (size_t)l * NQKV * DM;
        bf16* oh = woh + (size_t)l * DM * DM;
        bf16* ol = wol + (size_t)l * DM * DM;
        bf16* ih = wih + (size_t)l * DF * DM;
        bf16* il = wil + (size_t)l * DF * DM;
        bf16* mh = wmh + (size_t)l * DM * DF;
        bf16* ml = wml + (size_t)l * DM * DF;

        mkbias<<<(NQKV + 255) / 256, 256>>>(bq + l * DM, bv + l * DM, bqkv);

        ln_kernel<<<MROWS, 256>>>(h, g1 + l * DM, b1 + l * DM, hnh, hnl);

        mmagemm<<<gqkv, 256, GEMM_SMEM>>>(hnh, hnl, qh, ql, bqkv,
                                          nullptr, nullptr, qkv, nullptr, nullptr,
                                          MROWS, NQKV, DM, 0);

        attn_kernel<<<dim3(NH, NB), 256, ATT_SMEM_BYTES>>>(
            qkv, rel + (size_t)l * NDREL * NH, cth, ctl);

        mmagemm<<<g768, 256, GEMM_SMEM>>>(cth, ctl, oh, ol, bo + l * DM,
                                          h, lam1 + l * DM, h, nullptr, nullptr,
                                          MROWS, DM, DM, 2);

        ln_kernel<<<MROWS, 256>>>(h, g2 + l * DM, b2 + l * DM, hnh, hnl);

        mmagemm<<<g3072, 256, GEMM_SMEM>>>(hnh, hnl, ih, il, bi + l * DF,
                                           nullptr, nullptr, nullptr, fh, fl,
                                           MROWS, DF, DM, 1);

        mmagemm<<<g768, 256, GEMM_SMEM>>>(fh, fl, mh, ml, bmo + l * DM,
                                          h, lam2 + l * DM,
                                          (l == 2) ? (float*)d_out : h, nullptr, nullptr,
                                          MROWS, DM, DF, 2);
    }
}

// round 13
// speedup vs baseline: 1.3238x; 1.2873x over previous
#include <cuda_runtime.h>
#include <cuda_fp16.h>
#include <math.h>
#include <stdint.h>

// ---------------------------------------------------------------------------
// BEiT encoder: B=64, S=197, DM=768, H=12, D=64, DF=3072, L=3
// GEMMs: mma.sync fp16, A single-plane fp16, W = fp16 hi+lo (2 MMAs/product),
// BK=64, 3-stage cp.async (32KB/stage), 2 CTAs/SM, one barrier per chunk.
// ---------------------------------------------------------------------------

#define MROWS 12608
#define DM    768
#define DF    3072
#define NQKV  2304
#define SEQ   197
#define NB    64
#define NH    12
#define HD    64
#define NDREL 732

#define TM 128
#define TN 64
#define BK 64

// fp32 scratch
__device__ float g_h   [MROWS * DM];
__device__ float g_qkv [MROWS * NQKV];
__device__ float g_bqkv[NQKV];
// fp16 activation planes (single)
__device__ __half g_hn [MROWS * DM];
__device__ __half g_ctx[MROWS * DM];
__device__ __half g_f  [MROWS * DF];
// transposed weight planes [N][K], fp16 hi/lo
__device__ __half g_wqkv_hi[3 * NQKV * DM];
__device__ __half g_wqkv_lo[3 * NQKV * DM];
__device__ __half g_wo_hi  [3 * DM * DM];
__device__ __half g_wo_lo  [3 * DM * DM];
__device__ __half g_wi_hi  [3 * DF * DM];
__device__ __half g_wi_lo  [3 * DF * DM];
__device__ __half g_wmo_hi [3 * DM * DF];
__device__ __half g_wmo_lo [3 * DM * DF];

// ---------------------------------------------------------------------------
// helpers
// ---------------------------------------------------------------------------
__device__ __forceinline__ uint32_t smem_u32(const void* p) {
    uint32_t a;
    asm("{ .reg .u64 t; cvta.to.shared.u64 t, %1; cvt.u32.u64 %0, t; }"
        : "=r"(a) : "l"(p));
    return a;
}

#define SWZ(o) ((o) ^ (((o) >> 3) & 0x70))

__device__ __forceinline__ void ldm4(uint32_t* r, uint32_t addr) {
    asm volatile("ldmatrix.sync.aligned.m8n8.x4.shared.b16 {%0,%1,%2,%3}, [%4];"
                 : "=r"(r[0]), "=r"(r[1]), "=r"(r[2]), "=r"(r[3]) : "r"(addr));
}
__device__ __forceinline__ void mma16816(float* c, const uint32_t* a,
                                         uint32_t b0, uint32_t b1) {
    asm volatile(
        "mma.sync.aligned.m16n8k16.row.col.f32.f16.f16.f32 "
        "{%0,%1,%2,%3}, {%4,%5,%6,%7}, {%8,%9}, {%0,%1,%2,%3};"
        : "+f"(c[0]), "+f"(c[1]), "+f"(c[2]), "+f"(c[3])
        : "r"(a[0]), "r"(a[1]), "r"(a[2]), "r"(a[3]), "r"(b0), "r"(b1));
}
__device__ __forceinline__ void cpa16(uint32_t dst, const void* src, int sz) {
    asm volatile("cp.async.cg.shared.global [%0], [%1], 16, %2;"
                 :: "r"(dst), "l"(src), "r"(sz));
}
#define CP_COMMIT() asm volatile("cp.async.commit_group;" ::: "memory")
#define CP_WAIT1()  asm volatile("cp.async.wait_group 1;" ::: "memory")

// ldmatrix x4 address, 128B pitch SW128
__device__ __forceinline__ uint32_t swaddr(uint32_t base, int row, int ks, int lane) {
    uint32_t o = (uint32_t)(row + (lane & 15)) * 128 + (uint32_t)ks * 32 +
                 (uint32_t)((lane >> 4) << 4);
    return base + SWZ(o);
}
__device__ __forceinline__ uint32_t pkh2(float a, float b) {
    __half2 h = __floats2half2_rn(a, b);
    return *(uint32_t*)&h;
}

// ---------------------------------------------------------------------------
// Weight transpose + split: W[K][N] fp32 -> out_hi/lo[N][K] fp16
// ---------------------------------------------------------------------------
__global__ void convw(const float* __restrict__ W, __half* __restrict__ hi,
                      __half* __restrict__ lo, int K, int N)
{
    __shared__ float tile[32][33];
    int k0 = blockIdx.y * 32, n0 = blockIdx.x * 32;
    int tx = threadIdx.x, ty = threadIdx.y;
    #pragma unroll
    for (int i = ty; i < 32; i += 8)
        tile[i][tx] = W[(size_t)(k0 + i) * N + n0 + tx];
    __syncthreads();
    #pragma unroll
    for (int i = ty; i < 32; i += 8) {
        float v = tile[tx][i];
        __half h = __float2half_rn(v);
        size_t o = (size_t)(n0 + i) * K + k0 + tx;
        hi[o] = h;
        lo[o] = __float2half_rn(v - __half2float(h));
    }
}

__global__ void mkbias(const float* __restrict__ bq, const float* __restrict__ bv,
                       float* __restrict__ out)
{
    int i = blockIdx.x * 256 + threadIdx.x;
    if (i >= NQKV) return;
    out[i] = (i < DM) ? bq[i] : (i < 2 * DM) ? 0.f : bv[i - 2 * DM];
}

// ---------------------------------------------------------------------------
// GEMM: C = epi(A @ B^T), A[M][K] fp16, B planes [N][K] fp16 hi/lo
//  mode 0: fp32 C = v + bias ; 1: gelu -> Ch fp16 ; 2: fp32 C = res+(v+bias)*lam
//  CTA 128x64, BK=64, 3-stage cp.async, 8 warps (32x32), 1 barrier/chunk.
// ---------------------------------------------------------------------------
#define OFF_BH 16384
#define OFF_BL 24576
#define GSTAGE 32768
#define GEMM_SMEM (3 * GSTAGE)   // 96 KB -> 2 CTAs/SM

__global__ void __launch_bounds__(256, 2) mmagemm(
    const __half* __restrict__ A,
    const __half* __restrict__ Bhi, const __half* __restrict__ Blo,
    const float* __restrict__ bias, const float* __restrict__ res,
    const float* __restrict__ lam, float* __restrict__ C,
    __half* __restrict__ Ch,
    int M, int N, int K, int mode)
{
    extern __shared__ char smem[];
    uint32_t sb = smem_u32(smem);

    int t = threadIdx.x, wid = t >> 5, lane = t & 31;
    int bm = blockIdx.y * TM, bn = blockIdx.x * TN;

    int wm = wid >> 1, wn = wid & 1;       // 4 x 2 warps of 32x32
    int rmw = wm * 32, nbw = wn * 32;

    int ar[4], bw_r[2];
    uint32_t adsw[4], bdsw[2];
    #pragma unroll
    for (int j = 0; j < 4; j++) {
        int ci = j * 256 + t;
        ar[j] = ci >> 3;
        adsw[j] = SWZ((uint32_t)(ar[j] * 128 + (ci & 7) * 16));
    }
    #pragma unroll
    for (int j = 0; j < 2; j++) {
        int ci = j * 256 + t;
        bw_r[j] = ci >> 3;
        bdsw[j] = SWZ((uint32_t)(bw_r[j] * 128 + (ci & 7) * 16));
    }

    float acc[2][4][4];
    #pragma unroll
    for (int i = 0; i < 2; i++)
        #pragma unroll
        for (int j = 0; j < 4; j++)
            #pragma unroll
            for (int r = 0; r < 4; r++) acc[i][j][r] = 0.f;

    const int nk = K / BK;

    auto prefetch = [&](int kchunk, int stage) {
        uint32_t s0 = sb + stage * GSTAGE;
        int kc = kchunk * BK;
        #pragma unroll
        for (int j = 0; j < 4; j++) {
            int ci = j * 256 + t;
            int va = (bm + ar[j]) < M ? 16 : 0;
            size_t ao = (size_t)(bm + ar[j]) * K + kc + (ci & 7) * 8;
            cpa16(s0 + adsw[j], A + ao, va);
        }
        #pragma unroll
        for (int j = 0; j < 2; j++) {
            int ci = j * 256 + t;
            size_t bo = (size_t)(bn + bw_r[j]) * K + kc + (ci & 7) * 8;
            cpa16(s0 + OFF_BH + bdsw[j], Bhi + bo, 16);
            cpa16(s0 + OFF_BL + bdsw[j], Blo + bo, 16);
        }
    };

    prefetch(0, 0); CP_COMMIT();
    prefetch(1, 1); CP_COMMIT();

    for (int ki = 0; ki < nk; ki++) {
        CP_WAIT1();            // commit #ki retired => chunk ki resident
        __syncthreads();       // all warps done with compute ki-1 (stage free)
        if (ki + 2 < nk) prefetch(ki + 2, (ki + 2) % 3);
        CP_COMMIT();           // always commit (possibly empty) for accounting

        uint32_t sA  = sb + (ki % 3) * GSTAGE;
        uint32_t sBh = sA + OFF_BH, sBl = sA + OFF_BL;

        #pragma unroll
        for (int ks = 0; ks < 4; ks++) {
            uint32_t bh[8], bl[8], a4[2][4];
            #pragma unroll
            for (int j = 0; j < 2; j++) {
                ldm4(&bh[j * 4], swaddr(sBh, nbw + j * 16, ks, lane));
                ldm4(&bl[j * 4], swaddr(sBl, nbw + j * 16, ks, lane));
            }
            #pragma unroll
            for (int mi = 0; mi < 2; mi++)
                ldm4(a4[mi], swaddr(sA, rmw + mi * 16, ks, lane));
            #pragma unroll
            for (int mi = 0; mi < 2; mi++)
                #pragma unroll
                for (int j2 = 0; j2 < 4; j2++) {
                    int base = (j2 >> 1) * 4, sel = j2 & 1;
                    mma16816(acc[mi][j2], a4[mi], bh[base + sel], bh[base + 2 + sel]);
                    mma16816(acc[mi][j2], a4[mi], bl[base + sel], bl[base + 2 + sel]);
                }
        }
    }

    // ---- epilogue ----
    int r0 = lane >> 2, c0 = (lane & 3) * 2;
    #pragma unroll
    for (int mi = 0; mi < 2; mi++) {
        #pragma unroll
        for (int j2 = 0; j2 < 4; j2++) {
            int gn = bn + nbw + j2 * 8 + c0;
            float b0 = 0.f, b1 = 0.f;
            if (bias) { b0 = bias[gn]; b1 = bias[gn + 1]; }
            float l0 = 0.f, l1 = 0.f;
            if (mode == 2) { l0 = lam[gn]; l1 = lam[gn + 1]; }
            #pragma unroll
            for (int half = 0; half < 2; half++) {
                int gm = bm + rmw + mi * 16 + r0 + half * 8;
                if (gm >= M) continue;
                float vx = acc[mi][j2][half * 2 + 0] + b0;
                float vy = acc[mi][j2][half * 2 + 1] + b1;
                if (mode == 1) {
                    vx = 0.5f * vx * (1.0f + erff(vx * 0.70710678118654752f));
                    vy = 0.5f * vy * (1.0f + erff(vy * 0.70710678118654752f));
                    *(uint32_t*)(Ch + (size_t)gm * N + gn) = pkh2(vx, vy);
                } else {
                    if (mode == 2) {
                        const float2 rv = *(const float2*)(res + (size_t)gm * N + gn);
                        vx = rv.x + vx * l0;
                        vy = rv.y + vy * l1;
                    }
                    *(float2*)(C + (size_t)gm * N + gn) = make_float2(vx, vy);
                }
            }
        }
    }
}

// ---------------------------------------------------------------------------
// Patch embed
// ---------------------------------------------------------------------------
__global__ void embed_kernel(const float* __restrict__ x, const float* __restrict__ cls,
                             float* __restrict__ h)
{
    int i = blockIdx.x * 256 + threadIdx.x;
    if (i >= MROWS * DM) return;
    int c = i % DM;
    int s = (i / DM) % SEQ;
    int b = i / (DM * SEQ);
    h[i] = (s == 0) ? cls[c] : x[((size_t)(b * 196 + s - 1)) * DM + c];
}

// ---------------------------------------------------------------------------
// LayerNorm -> single fp16 plane
// ---------------------------------------------------------------------------
__global__ void ln_kernel(const float* __restrict__ x, const float* __restrict__ g,
                          const float* __restrict__ bta, __half* __restrict__ y)
{
    int row = blockIdx.x;
    const float* xr = x + (size_t)row * DM;
    int t = threadIdx.x;
    float v0 = xr[t], v1 = xr[t + 256], v2 = xr[t + 512];
    __shared__ float sh[8];

    float s = v0 + v1 + v2;
    #pragma unroll
    for (int o = 16; o; o >>= 1) s += __shfl_xor_sync(0xffffffffu, s, o);
    if ((t & 31) == 0) sh[t >> 5] = s;
    __syncthreads();
    if (t == 0) { float tot = 0.f; for (int i = 0; i < 8; i++) tot += sh[i]; sh[0] = tot; }
    __syncthreads();
    float mean = sh[0] * (1.0f / 768.0f);
    __syncthreads();

    float d0 = v0 - mean, d1 = v1 - mean, d2 = v2 - mean;
    s = d0 * d0 + d1 * d1 + d2 * d2;
    #pragma unroll
    for (int o = 16; o; o >>= 1) s += __shfl_xor_sync(0xffffffffu, s, o);
    if ((t & 31) == 0) sh[t >> 5] = s;
    __syncthreads();
    if (t == 0) { float tot = 0.f; for (int i = 0; i < 8; i++) tot += sh[i]; sh[0] = tot; }
    __syncthreads();
    float rstd = rsqrtf(sh[0] * (1.0f / 768.0f) + 1e-12f);

    size_t base = (size_t)row * DM;
    #pragma unroll
    for (int j = 0; j < 3; j++) {
        int col = t + j * 256;
        float d = (j == 0) ? d0 : (j == 1) ? d1 : d2;
        y[base + col] = __float2half_rn(d * rstd * g[col] + bta[col]);
    }
}

// ---------------------------------------------------------------------------
// Attention (R8 structure): qkv fused input; rel column + row/col LUT in smem.
// Output ctx as single fp16 plane.
// ---------------------------------------------------------------------------
#define KS_PITCH 65
#define ATT_SMEM_FLOATS (2 * SEQ * KS_PITCH + 8 * 64 + 8 * 200 + NDREL + 2 * SEQ)
#define ATT_SMEM_BYTES  (ATT_SMEM_FLOATS * 4)

__global__ void attn_kernel(const float* __restrict__ qkv, const float* __restrict__ rel,
                            __half* __restrict__ ch)
{
    int h = blockIdx.x, b = blockIdx.y;
    extern __shared__ float sm[];
    float* Ks   = sm;
    float* Vs   = sm + SEQ * KS_PITCH;
    float* qs   = sm + 2 * SEQ * KS_PITCH;
    float* Ps   = qs + 8 * 64;
    float* rels = Ps + 8 * 200;
    int*   rw   = (int*)(rels + NDREL);
    int*   cl   = rw + SEQ;

    int t = threadIdx.x;
    for (int idx = t; idx < SEQ * HD; idx += 256) {
        int kk = idx >> 6, d = idx & 63;
        size_t g = (size_t)(b * SEQ + kk) * NQKV + h * HD + d;
        Ks[kk * KS_PITCH + d] = qkv[g + DM];
        Vs[kk * KS_PITCH + d] = qkv[g + 2 * DM];
    }
    for (int idx = t; idx < NDREL; idx += 256)
        rels[idx] = rel[idx * NH + h];
    for (int idx = t; idx < SEQ; idx += 256) {
        rw[idx] = (idx > 0) ? (idx - 1) / 14 : 0;
        cl[idx] = (idx > 0) ? (idx - 1) % 14 : 0;
    }
    __syncthreads();

    int w = t >> 5, lane = t & 31;
    for (int q = w; q < SEQ; q += 8) {
        size_t qbase = (size_t)(b * SEQ + q) * NQKV + h * HD;
        qs[w * 64 + lane]      = qkv[qbase + lane];
        qs[w * 64 + lane + 32] = qkv[qbase + lane + 32];
        __syncwarp();

        int rwq = rw[q], clq = cl[q];
        bool isq0 = (q == 0);

        float s[7];
        float mx = -1e30f;
        #pragma unroll
        for (int j = 0; j < 7; j++) {
            int kk = lane + j * 32;
            float acc = -1e30f;
            if (kk < SEQ) {
                float v = 0.f;
                #pragma unroll
                for (int d = 0; d < HD; d++) v += qs[w * 64 + d] * Ks[kk * KS_PITCH + d];
                float bias;
                if (isq0)          bias = rels[(kk == 0) ? NDREL - 1 : NDREL - 3];
                else if (kk == 0)  bias = rels[NDREL - 2];
                else               bias = rels[(rwq - rw[kk] + 13) * 27 +
                                               (clq - cl[kk] + 13)];
                acc = v * 0.125f + bias;
            }
            s[j] = acc;
            mx = fmaxf(mx, acc);
        }
        #pragma unroll
        for (int o = 16; o; o >>= 1) mx = fmaxf(mx, __shfl_xor_sync(0xffffffffu, mx, o));

        float sum = 0.f;
        #pragma unroll
        for (int j = 0; j < 7; j++) {
            int kk = lane + j * 32;
            float e = (kk < SEQ) ? expf(s[j] - mx) : 0.f;
            s[j] = e;
            sum += e;
        }
        #pragma unroll
        for (int o = 16; o; o >>= 1) sum += __shfl_xor_sync(0xffffffffu, sum, o);
        float inv = 1.0f / sum;

        #pragma unroll
        for (int j = 0; j < 7; j++) {
            int kk = lane + j * 32;
            if (kk < SEQ) Ps[w * 200 + kk] = s[j] * inv;
        }
        __syncwarp();

        float a0 = 0.f, a1 = 0.f;
        for (int kk = 0; kk < SEQ; kk++) {
            float p = Ps[w * 200 + kk];
            a0 += p * Vs[kk * KS_PITCH + lane];
            a1 += p * Vs[kk * KS_PITCH + lane + 32];
        }
        size_t cbase = (size_t)(b * SEQ + q) * DM + h * HD;
        ch[cbase + lane]      = __float2half_rn(a0);
        ch[cbase + lane + 32] = __float2half_rn(a1);
        __syncwarp();
    }
}

// ---------------------------------------------------------------------------
// Orchestration
// ---------------------------------------------------------------------------
extern "C" void kernel_launch(void* const* d_in, const int* in_sizes, int n_in,
                              void* d_out, int out_size)
{
    const float* x    = (const float*)d_in[0];
    const float* cls  = (const float*)d_in[1];
    const float* g1   = (const float*)d_in[2];
    const float* b1   = (const float*)d_in[3];
    const float* Wq   = (const float*)d_in[4];
    const float* bq   = (const float*)d_in[5];
    const float* Wk   = (const float*)d_in[6];
    const float* Wv   = (const float*)d_in[7];
    const float* bv   = (const float*)d_in[8];
    const float* rel  = (const float*)d_in[9];
    const float* Wo   = (const float*)d_in[10];
    const float* bo   = (const float*)d_in[11];
    const float* lam1 = (const float*)d_in[12];
    const float* g2   = (const float*)d_in[13];
    const float* b2   = (const float*)d_in[14];
    const float* Wi   = (const float*)d_in[15];
    const float* bi   = (const float*)d_in[16];
    const float* Wmo  = (const float*)d_in[17];
    const float* bmo  = (const float*)d_in[18];
    const float* lam2 = (const float*)d_in[19];

    float *h, *qkv, *bqkv;
    __half *hn, *ctx, *f;
    __half *wqh, *wql, *woh, *wol, *wih, *wil, *wmh, *wml;
    cudaGetSymbolAddress((void**)&h,    g_h);
    cudaGetSymbolAddress((void**)&qkv,  g_qkv);
    cudaGetSymbolAddress((void**)&bqkv, g_bqkv);
    cudaGetSymbolAddress((void**)&hn,   g_hn);
    cudaGetSymbolAddress((void**)&ctx,  g_ctx);
    cudaGetSymbolAddress((void**)&f,    g_f);
    cudaGetSymbolAddress((void**)&wqh,  g_wqkv_hi);
    cudaGetSymbolAddress((void**)&wql,  g_wqkv_lo);
    cudaGetSymbolAddress((void**)&woh,  g_wo_hi);
    cudaGetSymbolAddress((void**)&wol,  g_wo_lo);
    cudaGetSymbolAddress((void**)&wih,  g_wi_hi);
    cudaGetSymbolAddress((void**)&wil,  g_wi_lo);
    cudaGetSymbolAddress((void**)&wmh,  g_wmo_hi);
    cudaGetSymbolAddress((void**)&wml,  g_wmo_lo);

    cudaFuncSetAttribute(attn_kernel, cudaFuncAttributeMaxDynamicSharedMemorySize,
                         ATT_SMEM_BYTES);
    cudaFuncSetAttribute(mmagemm, cudaFuncAttributeMaxDynamicSharedMemorySize,
                         GEMM_SMEM);

    dim3 cb(32, 8);
    for (int l = 0; l < 3; l++) {
        size_t wo  = (size_t)l * DM * DM;
        size_t wio = (size_t)l * DM * DF;
        __half* qh = wqh + (size_t)l * NQKV * DM;
        __half* ql = wql + (size_t)l * NQKV * DM;
        convw<<<dim3(DM / 32, DM / 32), cb>>>(Wq + wo, qh,               ql,               DM, DM);
        convw<<<dim3(DM / 32, DM / 32), cb>>>(Wk + wo, qh + DM * DM,     ql + DM * DM,     DM, DM);
        convw<<<dim3(DM / 32, DM / 32), cb>>>(Wv + wo, qh + 2 * DM * DM, ql + 2 * DM * DM, DM, DM);
        convw<<<dim3(DM / 32, DM / 32), cb>>>(Wo + wo, woh + wo, wol + wo, DM, DM);
        convw<<<dim3(DF / 32, DM / 32), cb>>>(Wi + wio, wih + (size_t)l * DF * DM,
                                              wil + (size_t)l * DF * DM, DM, DF);
        convw<<<dim3(DM / 32, DF / 32), cb>>>(Wmo + wio, wmh + (size_t)l * DM * DF,
                                              wml + (size_t)l * DM * DF, DF, DM);
    }

    embed_kernel<<<(MROWS * DM + 255) / 256, 256>>>(x, cls, h);

    int mt = (MROWS + TM - 1) / TM;        // 99
    dim3 gqkv(NQKV / TN, mt);              // (36, 99)
    dim3 g768(DM / TN, mt);                // (12, 99)
    dim3 g3072(DF / TN, mt);               // (48, 99)

    for (int l = 0; l < 3; l++) {
        __half* qh = wqh + (size_t)l * NQKV * DM;
        __half* ql = wql + (size_t)l * NQKV * DM;
        __half* oh = woh + (size_t)l * DM * DM;
        __half* ol = wol + (size_t)l * DM * DM;
        __half* ih = wih + (size_t)l * DF * DM;
        __half* il = wil + (size_t)l * DF * DM;
        __half* mh = wmh + (size_t)l * DM * DF;
        __half* ml = wml + (size_t)l * DM * DF;

        mkbias<<<(NQKV + 255) / 256, 256>>>(bq + l * DM, bv + l * DM, bqkv);

        ln_kernel<<<MROWS, 256>>>(h, g1 + l * DM, b1 + l * DM, hn);

        mmagemm<<<gqkv, 256, GEMM_SMEM>>>(hn, qh, ql, bqkv,
                                          nullptr, nullptr, qkv, nullptr,
                                          MROWS, NQKV, DM, 0);

        attn_kernel<<<dim3(NH, NB), 256, ATT_SMEM_BYTES>>>(
            qkv, rel + (size_t)l * NDREL * NH, ctx);

        mmagemm<<<g768, 256, GEMM_SMEM>>>(ctx, oh, ol, bo + l * DM,
                                          h, lam1 + l * DM, h, nullptr,
                                          MROWS, DM, DM, 2);

        ln_kernel<<<MROWS, 256>>>(h, g2 + l * DM, b2 + l * DM, hn);

        mmagemm<<<g3072, 256, GEMM_SMEM>>>(hn, ih, il, bi + l * DF,
                                           nullptr, nullptr, nullptr, f,
                                           MROWS, DF, DM, 1);

        mmagemm<<<g768, 256, GEMM_SMEM>>>(f, mh, ml, bmo + l * DM,
                                          h, lam2 + l * DM,
                                          (l == 2) ? (float*)d_out : h, nullptr,
                                          MROWS, DM, DF, 2);
    }
}

// round 17
// speedup vs baseline: 1.6874x; 1.2747x over previous
#include <cuda_runtime.h>
#include <cuda_fp16.h>
#include <math.h>
#include <stdint.h>

// ---------------------------------------------------------------------------
// BEiT encoder: B=64, S=197, DM=768, H=12, D=64, DF=3072, L=3
// GEMMs: mma.sync fp16, A and W single fp16 planes (1 MMA/product),
// BK=64, 3-stage cp.async (24KB/stage), 2 CTAs/SM, one barrier per chunk.
// ---------------------------------------------------------------------------

#define MROWS 12608
#define DM    768
#define DF    3072
#define NQKV  2304
#define SEQ   197
#define NB    64
#define NH    12
#define HD    64
#define NDREL 732

#define TM 128
#define TN 64
#define BK 64

// fp32 scratch
__device__ float g_h   [MROWS * DM];
__device__ float g_qkv [MROWS * NQKV];
__device__ float g_bqkv[NQKV];
// fp16 activation planes
__device__ __half g_hn [MROWS * DM];
__device__ __half g_ctx[MROWS * DM];
__device__ __half g_f  [MROWS * DF];
// transposed weight planes [N][K], single fp16
__device__ __half g_wqkv[3 * NQKV * DM];
__device__ __half g_wo  [3 * DM * DM];
__device__ __half g_wi  [3 * DF * DM];
__device__ __half g_wmo [3 * DM * DF];

// ---------------------------------------------------------------------------
// helpers
// ---------------------------------------------------------------------------
__device__ __forceinline__ uint32_t smem_u32(const void* p) {
    uint32_t a;
    asm("{ .reg .u64 t; cvta.to.shared.u64 t, %1; cvt.u32.u64 %0, t; }"
        : "=r"(a) : "l"(p));
    return a;
}

#define SWZ(o) ((o) ^ (((o) >> 3) & 0x70))

__device__ __forceinline__ void ldm4(uint32_t* r, uint32_t addr) {
    asm volatile("ldmatrix.sync.aligned.m8n8.x4.shared.b16 {%0,%1,%2,%3}, [%4];"
                 : "=r"(r[0]), "=r"(r[1]), "=r"(r[2]), "=r"(r[3]) : "r"(addr));
}
__device__ __forceinline__ void mma16816(float* c, const uint32_t* a,
                                         uint32_t b0, uint32_t b1) {
    asm volatile(
        "mma.sync.aligned.m16n8k16.row.col.f32.f16.f16.f32 "
        "{%0,%1,%2,%3}, {%4,%5,%6,%7}, {%8,%9}, {%0,%1,%2,%3};"
        : "+f"(c[0]), "+f"(c[1]), "+f"(c[2]), "+f"(c[3])
        : "r"(a[0]), "r"(a[1]), "r"(a[2]), "r"(a[3]), "r"(b0), "r"(b1));
}
__device__ __forceinline__ void cpa16(uint32_t dst, const void* src, int sz) {
    asm volatile("cp.async.cg.shared.global [%0], [%1], 16, %2;"
                 :: "r"(dst), "l"(src), "r"(sz));
}
#define CP_COMMIT() asm volatile("cp.async.commit_group;" ::: "memory")
#define CP_WAIT1()  asm volatile("cp.async.wait_group 1;" ::: "memory")

// ldmatrix x4 address, 128B pitch SW128
__device__ __forceinline__ uint32_t swaddr(uint32_t base, int row, int ks, int lane) {
    uint32_t o = (uint32_t)(row + (lane & 15)) * 128 + (uint32_t)ks * 32 +
                 (uint32_t)((lane >> 4) << 4);
    return base + SWZ(o);
}
__device__ __forceinline__ uint32_t pkh2(float a, float b) {
    __half2 h = __floats2half2_rn(a, b);
    return *(uint32_t*)&h;
}

// ---------------------------------------------------------------------------
// Weight transpose: W[K][N] fp32 -> out[N][K] fp16
// ---------------------------------------------------------------------------
__global__ void convw(const float* __restrict__ W, __half* __restrict__ out,
                      int K, int N)
{
    __shared__ float tile[32][33];
    int k0 = blockIdx.y * 32, n0 = blockIdx.x * 32;
    int tx = threadIdx.x, ty = threadIdx.y;
    #pragma unroll
    for (int i = ty; i < 32; i += 8)
        tile[i][tx] = W[(size_t)(k0 + i) * N + n0 + tx];
    __syncthreads();
    #pragma unroll
    for (int i = ty; i < 32; i += 8)
        out[(size_t)(n0 + i) * K + k0 + tx] = __float2half_rn(tile[tx][i]);
}

__global__ void mkbias(const float* __restrict__ bq, const float* __restrict__ bv,
                       float* __restrict__ out)
{
    int i = blockIdx.x * 256 + threadIdx.x;
    if (i >= NQKV) return;
    out[i] = (i < DM) ? bq[i] : (i < 2 * DM) ? 0.f : bv[i - 2 * DM];
}

// ---------------------------------------------------------------------------
// GEMM: C = epi(A @ B^T), A[M][K] fp16, B[N][K] fp16
//  mode 0: fp32 C = v + bias ; 1: gelu -> Ch fp16 ; 2: fp32 C = res+(v+bias)*lam
//  CTA 128x64, BK=64, 3-stage cp.async, 8 warps (32x32), 1 barrier/chunk.
// ---------------------------------------------------------------------------
#define OFF_B  16384
#define GSTAGE 24576
#define GEMM_SMEM (3 * GSTAGE)   // 73728 -> 2 CTAs/SM

__global__ void __launch_bounds__(256, 2) mmagemm(
    const __half* __restrict__ A, const __half* __restrict__ B,
    const float* __restrict__ bias, const float* __restrict__ res,
    const float* __restrict__ lam, float* __restrict__ C,
    __half* __restrict__ Ch,
    int M, int N, int K, int mode)
{
    extern __shared__ char smem[];
    uint32_t sb = smem_u32(smem);

    int t = threadIdx.x, wid = t >> 5, lane = t & 31;
    int bm = blockIdx.y * TM, bn = blockIdx.x * TN;

    int wm = wid >> 1, wn = wid & 1;       // 4 x 2 warps of 32x32
    int rmw = wm * 32, nbw = wn * 32;

    int ar[4], bw_r[2];
    uint32_t adsw[4], bdsw[2];
    #pragma unroll
    for (int j = 0; j < 4; j++) {
        int ci = j * 256 + t;
        ar[j] = ci >> 3;
        adsw[j] = SWZ((uint32_t)(ar[j] * 128 + (ci & 7) * 16));
    }
    #pragma unroll
    for (int j = 0; j < 2; j++) {
        int ci = j * 256 + t;
        bw_r[j] = ci >> 3;
        bdsw[j] = SWZ((uint32_t)(bw_r[j] * 128 + (ci & 7) * 16));
    }

    float acc[2][4][4];
    #pragma unroll
    for (int i = 0; i < 2; i++)
        #pragma unroll
        for (int j = 0; j < 4; j++)
            #pragma unroll
            for (int r = 0; r < 4; r++) acc[i][j][r] = 0.f;

    const int nk = K / BK;

    auto prefetch = [&](int kchunk, int stage) {
        uint32_t s0 = sb + stage * GSTAGE;
        int kc = kchunk * BK;
        #pragma unroll
        for (int j = 0; j < 4; j++) {
            int ci = j * 256 + t;
            int va = (bm + ar[j]) < M ? 16 : 0;
            size_t ao = (size_t)(bm + ar[j]) * K + kc + (ci & 7) * 8;
            cpa16(s0 + adsw[j], A + ao, va);
        }
        #pragma unroll
        for (int j = 0; j < 2; j++) {
            int ci = j * 256 + t;
            size_t bo = (size_t)(bn + bw_r[j]) * K + kc + (ci & 7) * 8;
            cpa16(s0 + OFF_B + bdsw[j], B + bo, 16);
        }
    };

    prefetch(0, 0); CP_COMMIT();
    prefetch(1, 1); CP_COMMIT();

    for (int ki = 0; ki < nk; ki++) {
        CP_WAIT1();
        __syncthreads();
        if (ki + 2 < nk) prefetch(ki + 2, (ki + 2) % 3);
        CP_COMMIT();

        uint32_t sA = sb + (ki % 3) * GSTAGE;
        uint32_t sB = sA + OFF_B;

        #pragma unroll
        for (int ks = 0; ks < 4; ks++) {
            uint32_t bh[8], a4[2][4];
            #pragma unroll
            for (int j = 0; j < 2; j++)
                ldm4(&bh[j * 4], swaddr(sB, nbw + j * 16, ks, lane));
            #pragma unroll
            for (int mi = 0; mi < 2; mi++)
                ldm4(a4[mi], swaddr(sA, rmw + mi * 16, ks, lane));
            #pragma unroll
            for (int mi = 0; mi < 2; mi++)
                #pragma unroll
                for (int j2 = 0; j2 < 4; j2++) {
                    int base = (j2 >> 1) * 4, sel = j2 & 1;
                    mma16816(acc[mi][j2], a4[mi], bh[base + sel], bh[base + 2 + sel]);
                }
        }
    }

    // ---- epilogue ----
    int r0 = lane >> 2, c0 = (lane & 3) * 2;
    #pragma unroll
    for (int mi = 0; mi < 2; mi++) {
        #pragma unroll
        for (int j2 = 0; j2 < 4; j2++) {
            int gn = bn + nbw + j2 * 8 + c0;
            float b0 = 0.f, b1 = 0.f;
            if (bias) { b0 = bias[gn]; b1 = bias[gn + 1]; }
            float l0 = 0.f, l1 = 0.f;
            if (mode == 2) { l0 = lam[gn]; l1 = lam[gn + 1]; }
            #pragma unroll
            for (int half = 0; half < 2; half++) {
                int gm = bm + rmw + mi * 16 + r0 + half * 8;
                if (gm >= M) continue;
                float vx = acc[mi][j2][half * 2 + 0] + b0;
                float vy = acc[mi][j2][half * 2 + 1] + b1;
                if (mode == 1) {
                    vx = 0.5f * vx * (1.0f + erff(vx * 0.70710678118654752f));
                    vy = 0.5f * vy * (1.0f + erff(vy * 0.70710678118654752f));
                    *(uint32_t*)(Ch + (size_t)gm * N + gn) = pkh2(vx, vy);
                } else {
                    if (mode == 2) {
                        const float2 rv = *(const float2*)(res + (size_t)gm * N + gn);
                        vx = rv.x + vx * l0;
                        vy = rv.y + vy * l1;
                    }
                    *(float2*)(C + (size_t)gm * N + gn) = make_float2(vx, vy);
                }
            }
        }
    }
}

// ---------------------------------------------------------------------------
// Patch embed
// ---------------------------------------------------------------------------
__global__ void embed_kernel(const float* __restrict__ x, const float* __restrict__ cls,
                             float* __restrict__ h)
{
    int i = blockIdx.x * 256 + threadIdx.x;
    if (i >= MROWS * DM) return;
    int c = i % DM;
    int s = (i / DM) % SEQ;
    int b = i / (DM * SEQ);
    h[i] = (s == 0) ? cls[c] : x[((size_t)(b * 196 + s - 1)) * DM + c];
}

// ---------------------------------------------------------------------------
// LayerNorm -> single fp16 plane
// ---------------------------------------------------------------------------
__global__ void ln_kernel(const float* __restrict__ x, const float* __restrict__ g,
                          const float* __restrict__ bta, __half* __restrict__ y)
{
    int row = blockIdx.x;
    const float* xr = x + (size_t)row * DM;
    int t = threadIdx.x;
    float v0 = xr[t], v1 = xr[t + 256], v2 = xr[t + 512];
    __shared__ float sh[8];

    float s = v0 + v1 + v2;
    #pragma unroll
    for (int o = 16; o; o >>= 1) s += __shfl_xor_sync(0xffffffffu, s, o);
    if ((t & 31) == 0) sh[t >> 5] = s;
    __syncthreads();
    if (t == 0) { float tot = 0.f; for (int i = 0; i < 8; i++) tot += sh[i]; sh[0] = tot; }
    __syncthreads();
    float mean = sh[0] * (1.0f / 768.0f);
    __syncthreads();

    float d0 = v0 - mean, d1 = v1 - mean, d2 = v2 - mean;
    s = d0 * d0 + d1 * d1 + d2 * d2;
    #pragma unroll
    for (int o = 16; o; o >>= 1) s += __shfl_xor_sync(0xffffffffu, s, o);
    if ((t & 31) == 0) sh[t >> 5] = s;
    __syncthreads();
    if (t == 0) { float tot = 0.f; for (int i = 0; i < 8; i++) tot += sh[i]; sh[0] = tot; }
    __syncthreads();
    float rstd = rsqrtf(sh[0] * (1.0f / 768.0f) + 1e-12f);

    size_t base = (size_t)row * DM;
    #pragma unroll
    for (int j = 0; j < 3; j++) {
        int col = t + j * 256;
        float d = (j == 0) ? d0 : (j == 1) ? d1 : d2;
        y[base + col] = __float2half_rn(d * rstd * g[col] + bta[col]);
    }
}

// ---------------------------------------------------------------------------
// Attention (R8 structure): qkv fused input; rel column + row/col LUT in smem.
// ---------------------------------------------------------------------------
#define KS_PITCH 65
#define ATT_SMEM_FLOATS (2 * SEQ * KS_PITCH + 8 * 64 + 8 * 200 + NDREL + 2 * SEQ)
#define ATT_SMEM_BYTES  (ATT_SMEM_FLOATS * 4)

__global__ void attn_kernel(const float* __restrict__ qkv, const float* __restrict__ rel,
                            __half* __restrict__ ch)
{
    int h = blockIdx.x, b = blockIdx.y;
    extern __shared__ float sm[];
    float* Ks   = sm;
    float* Vs   = sm + SEQ * KS_PITCH;
    float* qs   = sm + 2 * SEQ * KS_PITCH;
    float* Ps   = qs + 8 * 64;
    float* rels = Ps + 8 * 200;
    int*   rw   = (int*)(rels + NDREL);
    int*   cl   = rw + SEQ;

    int t = threadIdx.x;
    for (int idx = t; idx < SEQ * HD; idx += 256) {
        int kk = idx >> 6, d = idx & 63;
        size_t g = (size_t)(b * SEQ + kk) * NQKV + h * HD + d;
        Ks[kk * KS_PITCH + d] = qkv[g + DM];
        Vs[kk * KS_PITCH + d] = qkv[g + 2 * DM];
    }
    for (int idx = t; idx < NDREL; idx += 256)
        rels[idx] = rel[idx * NH + h];
    for (int idx = t; idx < SEQ; idx += 256) {
        rw[idx] = (idx > 0) ? (idx - 1) / 14 : 0;
        cl[idx] = (idx > 0) ? (idx - 1) % 14 : 0;
    }
    __syncthreads();

    int w = t >> 5, lane = t & 31;
    for (int q = w; q < SEQ; q += 8) {
        size_t qbase = (size_t)(b * SEQ + q) * NQKV + h * HD;
        qs[w * 64 + lane]      = qkv[qbase + lane];
        qs[w * 64 + lane + 32] = qkv[qbase + lane + 32];
        __syncwarp();

        int rwq = rw[q], clq = cl[q];
        bool isq0 = (q == 0);

        float s[7];
        float mx = -1e30f;
        #pragma unroll
        for (int j = 0; j < 7; j++) {
            int kk = lane + j * 32;
            float acc = -1e30f;
            if (kk < SEQ) {
                float v = 0.f;
                #pragma unroll
                for (int d = 0; d < HD; d++) v += qs[w * 64 + d] * Ks[kk * KS_PITCH + d];
                float bias;
                if (isq0)          bias = rels[(kk == 0) ? NDREL - 1 : NDREL - 3];
                else if (kk == 0)  bias = rels[NDREL - 2];
                else               bias = rels[(rwq - rw[kk] + 13) * 27 +
                                               (clq - cl[kk] + 13)];
                acc = v * 0.125f + bias;
            }
            s[j] = acc;
            mx = fmaxf(mx, acc);
        }
        #pragma unroll
        for (int o = 16; o; o >>= 1) mx = fmaxf(mx, __shfl_xor_sync(0xffffffffu, mx, o));

        float sum = 0.f;
        #pragma unroll
        for (int j = 0; j < 7; j++) {
            int kk = lane + j * 32;
            float e = (kk < SEQ) ? expf(s[j] - mx) : 0.f;
            s[j] = e;
            sum += e;
        }
        #pragma unroll
        for (int o = 16; o; o >>= 1) sum += __shfl_xor_sync(0xffffffffu, sum, o);
        float inv = 1.0f / sum;

        #pragma unroll
        for (int j = 0; j < 7; j++) {
            int kk = lane + j * 32;
            if (kk < SEQ) Ps[w * 200 + kk] = s[j] * inv;
        }
        __syncwarp();

        float a0 = 0.f, a1 = 0.f;
        for (int kk = 0; kk < SEQ; kk++) {
            float p = Ps[w * 200 + kk];
            a0 += p * Vs[kk * KS_PITCH + lane];
            a1 += p * Vs[kk * KS_PITCH + lane + 32];
        }
        size_t cbase = (size_t)(b * SEQ + q) * DM + h * HD;
        ch[cbase + lane]      = __float2half_rn(a0);
        ch[cbase + lane + 32] = __float2half_rn(a1);
        __syncwarp();
    }
}

// ---------------------------------------------------------------------------
// Orchestration
// ---------------------------------------------------------------------------
extern "C" void kernel_launch(void* const* d_in, const int* in_sizes, int n_in,
                              void* d_out, int out_size)
{
    const float* x    = (const float*)d_in[0];
    const float* cls  = (const float*)d_in[1];
    const float* g1   = (const float*)d_in[2];
    const float* b1   = (const float*)d_in[3];
    const float* Wq   = (const float*)d_in[4];
    const float* bq   = (const float*)d_in[5];
    const float* Wk   = (const float*)d_in[6];
    const float* Wv   = (const float*)d_in[7];
    const float* bv   = (const float*)d_in[8];
    const float* rel  = (const float*)d_in[9];
    const float* Wo   = (const float*)d_in[10];
    const float* bo   = (const float*)d_in[11];
    const float* lam1 = (const float*)d_in[12];
    const float* g2   = (const float*)d_in[13];
    const float* b2   = (const float*)d_in[14];
    const float* Wi   = (const float*)d_in[15];
    const float* bi   = (const float*)d_in[16];
    const float* Wmo  = (const float*)d_in[17];
    const float* bmo  = (const float*)d_in[18];
    const float* lam2 = (const float*)d_in[19];

    float *h, *qkv, *bqkv;
    __half *hn, *ctx, *f;
    __half *wq_, *wo_, *wi_, *wm_;
    cudaGetSymbolAddress((void**)&h,    g_h);
    cudaGetSymbolAddress((void**)&qkv,  g_qkv);
    cudaGetSymbolAddress((void**)&bqkv, g_bqkv);
    cudaGetSymbolAddress((void**)&hn,   g_hn);
    cudaGetSymbolAddress((void**)&ctx,  g_ctx);
    cudaGetSymbolAddress((void**)&f,    g_f);
    cudaGetSymbolAddress((void**)&wq_,  g_wqkv);
    cudaGetSymbolAddress((void**)&wo_,  g_wo);
    cudaGetSymbolAddress((void**)&wi_,  g_wi);
    cudaGetSymbolAddress((void**)&wm_,  g_wmo);

    cudaFuncSetAttribute(attn_kernel, cudaFuncAttributeMaxDynamicSharedMemorySize,
                         ATT_SMEM_BYTES);
    cudaFuncSetAttribute(mmagemm, cudaFuncAttributeMaxDynamicSharedMemorySize,
                         GEMM_SMEM);

    dim3 cb(32, 8);
    for (int l = 0; l < 3; l++) {
        size_t wo  = (size_t)l * DM * DM;
        size_t wio = (size_t)l * DM * DF;
        __half* qh = wq_ + (size_t)l * NQKV * DM;
        convw<<<dim3(DM / 32, DM / 32), cb>>>(Wq + wo, qh,               DM, DM);
        convw<<<dim3(DM / 32, DM / 32), cb>>>(Wk + wo, qh + DM * DM,     DM, DM);
        convw<<<dim3(DM / 32, DM / 32), cb>>>(Wv + wo, qh + 2 * DM * DM, DM, DM);
        convw<<<dim3(DM / 32, DM / 32), cb>>>(Wo + wo, wo_ + wo, DM, DM);
        convw<<<dim3(DF / 32, DM / 32), cb>>>(Wi + wio, wi_ + (size_t)l * DF * DM, DM, DF);
        convw<<<dim3(DM / 32, DF / 32), cb>>>(Wmo + wio, wm_ + (size_t)l * DM * DF, DF, DM);
    }

    embed_kernel<<<(MROWS * DM + 255) / 256, 256>>>(x, cls, h);

    int mt = (MROWS + TM - 1) / TM;        // 99
    dim3 gqkv(NQKV / TN, mt);              // (36, 99)
    dim3 g768(DM / TN, mt);                // (12, 99)
    dim3 g3072(DF / TN, mt);               // (48, 99)

    for (int l = 0; l < 3; l++) {
        __half* qh = wq_ + (size_t)l * NQKV * DM;
        __half* oh = wo_ + (size_t)l * DM * DM;
        __half* ih = wi_ + (size_t)l * DF * DM;
        __half* mh = wm_ + (size_t)l * DM * DF;

        mkbias<<<(NQKV + 255) / 256, 256>>>(bq + l * DM, bv + l * DM, bqkv);

        ln_kernel<<<MROWS, 256>>>(h, g1 + l * DM, b1 + l * DM, hn);

        mmagemm<<<gqkv, 256, GEMM_SMEM>>>(hn, qh, bqkv,
                                          nullptr, nullptr, qkv, nullptr,
                                          MROWS, NQKV, DM, 0);

        attn_kernel<<<dim3(NH, NB), 256, ATT_SMEM_BYTES>>>(
            qkv, rel + (size_t)l * NDREL * NH, ctx);

        mmagemm<<<g768, 256, GEMM_SMEM>>>(ctx, oh, bo + l * DM,
                                          h, lam1 + l * DM, h, nullptr,
                                          MROWS, DM, DM, 2);

        ln_kernel<<<MROWS, 256>>>(h, g2 + l * DM, b2 + l * DM, hn);

        mmagemm<<<g3072, 256, GEMM_SMEM>>>(hn, ih, bi + l * DF,
                                           nullptr, nullptr, nullptr, f,
                                           MROWS, DF, DM, 1);

        mmagemm<<<g768, 256, GEMM_SMEM>>>(f, mh, bmo + l * DM,
                                          h, lam2 + l * DM,
                                          (l == 2) ? (float*)d_out : h, nullptr,
                                          MROWS, DM, DF, 2);
    }
}